// round 8
// baseline (speedup 1.0000x reference)
#include <cuda_runtime.h>
#include <cuda_bf16.h>
#include <math.h>
#include <stdint.h>

// Problem constants
#define T_   2048
#define HID_ 4096
#define NH_  16
#define D_   256
#define QKV_N_ (3 * HID_)   // 12288
#define EPS_ 1e-6f

// ---------------------------------------------------------------------------
// Scratch (device globals — no allocation allowed)
// ---------------------------------------------------------------------------
__device__ float          g_qkv    [T_ * QKV_N_];     // fp32 qkv projection
__device__ __nv_bfloat16  g_hidhi  [T_ * HID_];       // hidden split planes
__device__ __nv_bfloat16  g_hidlo  [T_ * HID_];
__device__ __nv_bfloat16  g_wqkvThi[QKV_N_ * HID_];   // w_qkv^T planes [N][K]
__device__ __nv_bfloat16  g_wqkvTlo[QKV_N_ * HID_];
__device__ __nv_bfloat16  g_woThi  [HID_ * HID_];     // w_o^T planes [N][K]
__device__ __nv_bfloat16  g_woTlo  [HID_ * HID_];
__device__ uint32_t       g_q32    [NH_ * T_ * D_];   // packed q/k/v for attn
__device__ uint32_t       g_k32    [NH_ * T_ * D_];
__device__ uint32_t       g_v32    [NH_ * T_ * D_];
__device__ __nv_bfloat16  g_attnhi [T_ * HID_];       // attn output planes
__device__ __nv_bfloat16  g_attnlo [T_ * HID_];
__device__ float2         g_rope   [T_ * (D_ / 2)];

// ---------------------------------------------------------------------------
// Common helpers
// ---------------------------------------------------------------------------
__device__ __forceinline__ void split_bf16(float v, __nv_bfloat16& h, __nv_bfloat16& l) {
    h = __float2bfloat16(v);
    l = __float2bfloat16(v - __bfloat162float(h));
}
__device__ __forceinline__ uint32_t pack_split(float x) {
    __nv_bfloat16 hb, lb; split_bf16(x, hb, lb);
    return ((uint32_t)__bfloat16_as_ushort(lb) << 16) | (uint32_t)__bfloat16_as_ushort(hb);
}
#define MAIN2(u0, u1)  __byte_perm((u0), (u1), 0x5410)
#define RESID2(u0, u1) __byte_perm((u0), (u1), 0x7632)

__device__ __forceinline__ void mma_bf16(float c[4],
                                         uint32_t a0, uint32_t a1, uint32_t a2, uint32_t a3,
                                         uint32_t b0, uint32_t b1) {
    asm volatile(
        "mma.sync.aligned.m16n8k16.row.col.f32.bf16.bf16.f32 "
        "{%0,%1,%2,%3}, {%4,%5,%6,%7}, {%8,%9}, {%0,%1,%2,%3};"
        : "+f"(c[0]), "+f"(c[1]), "+f"(c[2]), "+f"(c[3])
        : "r"(a0), "r"(a1), "r"(a2), "r"(a3), "r"(b0), "r"(b1));
}

__device__ __forceinline__ void ldsm_x4(uint32_t r[4], uint32_t addr) {
    asm volatile("ldmatrix.sync.aligned.m8n8.x4.shared.b16 {%0,%1,%2,%3}, [%4];"
                 : "=r"(r[0]), "=r"(r[1]), "=r"(r[2]), "=r"(r[3]) : "r"(addr));
}

#define CP_ASYNC16(smem_u32, gptr) \
    asm volatile("cp.async.cg.shared.global [%0], [%1], 16;" :: "r"(smem_u32), "l"(gptr))
#define CP_COMMIT() asm volatile("cp.async.commit_group;")
#define CP_WAIT(n)  asm volatile("cp.async.wait_group %0;" :: "n"(n))

// ---------------------------------------------------------------------------
// Pre-pass kernels: split fp32 into bf16 hi/lo planes (optionally transposed)
// ---------------------------------------------------------------------------
__global__ __launch_bounds__(256) void split_planes(
    const float* __restrict__ src, __nv_bfloat16* __restrict__ dhi,
    __nv_bfloat16* __restrict__ dlo, int n4)
{
    int i = blockIdx.x * 256 + threadIdx.x;
    int stride = gridDim.x * 256;
    for (; i < n4; i += stride) {
        float4 v = ((const float4*)src)[i];
        __nv_bfloat16 h0,l0,h1,l1,h2,l2,h3,l3;
        split_bf16(v.x,h0,l0); split_bf16(v.y,h1,l1);
        split_bf16(v.z,h2,l2); split_bf16(v.w,h3,l3);
        ((__nv_bfloat162*)dhi)[2*i]   = __nv_bfloat162(h0,h1);
        ((__nv_bfloat162*)dhi)[2*i+1] = __nv_bfloat162(h2,h3);
        ((__nv_bfloat162*)dlo)[2*i]   = __nv_bfloat162(l0,l1);
        ((__nv_bfloat162*)dlo)[2*i+1] = __nv_bfloat162(l2,l3);
    }
}

// src fp32 [R][C] -> dhi/dlo bf16 [C][R]
__global__ __launch_bounds__(256) void transpose_split(
    const float* __restrict__ src, __nv_bfloat16* __restrict__ dhi,
    __nv_bfloat16* __restrict__ dlo, int R, int C)
{
    __shared__ float tile[32][33];
    const int tx = threadIdx.x & 31, ty = threadIdx.x >> 5;
    #pragma unroll
    for (int j = 0; j < 4; j++) {
        int r = blockIdx.y * 32 + ty + j * 8;
        tile[ty + j * 8][tx] = src[(size_t)r * C + blockIdx.x * 32 + tx];
    }
    __syncthreads();
    #pragma unroll
    for (int j = 0; j < 4; j++) {
        int c = blockIdx.x * 32 + ty + j * 8;   // out row
        int r = blockIdx.y * 32 + tx;           // out col
        float v = tile[tx][ty + j * 8];
        __nv_bfloat16 h, l; split_bf16(v, h, l);
        dhi[(size_t)c * R + r] = h;
        dlo[(size_t)c * R + r] = l;
    }
}

// ---------------------------------------------------------------------------
// bf16-split GEMM via ldmatrix + mma.m16n8k16.
// C_fp32[M,N] = A[M,K] @ B[N,K]^T. A,B given as separate hi/lo planes.
// BM=BN=128, BK=32. 8 warps (2x4), warp tile 64x32. Double-buffered cp.async.
// Grid: (M/128, N/128)  -- M fastest so a wave shares B slices (L2 reuse).
// ---------------------------------------------------------------------------
#define BK       32
#define ASTRIDE  40                      // row stride in bf16 elems (80B)
#define PLB      (128 * ASTRIDE * 2)     // plane bytes = 10240
#define STAGE_B  (4 * PLB)               // 40960
#define GEMM_SMEM (2 * STAGE_B)          // 81920

__global__ __launch_bounds__(256) void gemm_lds(
    const __nv_bfloat16* __restrict__ Ahi, const __nv_bfloat16* __restrict__ Alo,
    const __nv_bfloat16* __restrict__ Bhi, const __nv_bfloat16* __restrict__ Blo,
    float* __restrict__ C, int M, int N, int K)
{
    extern __shared__ char smem[];
    const uint32_t sb = (uint32_t)__cvta_generic_to_shared(smem);

    const int tid  = threadIdx.x;
    const int wid  = tid >> 5, lane = tid & 31;
    const int bm   = blockIdx.x * 128;
    const int bn   = blockIdx.y * 128;
    const int wm   = (wid >> 2) * 64;
    const int wn   = (wid & 3)  * 32;
    const int g    = lane >> 2;
    const int tig  = lane & 3;
    const int lrow = lane & 15;
    const int lcol8 = (lane >> 4) * 8;

    float acc[4][4][4];
    #pragma unroll
    for (int i = 0; i < 4; i++)
        #pragma unroll
        for (int j = 0; j < 4; j++)
            #pragma unroll
            for (int r = 0; r < 4; r++) acc[i][j][r] = 0.f;

    auto load_chunk = [&](int stg, int c) {
        const int k0 = c * BK;
        const uint32_t tb = sb + stg * STAGE_B;
        #pragma unroll
        for (int i = tid; i < 512; i += 256) {           // A planes: 128r x 4x16B
            const int row = i >> 2, col = (i & 3) * 8;
            const uint32_t off = (uint32_t)(row * ASTRIDE + col) * 2;
            const size_t gi = (size_t)(bm + row) * K + k0 + col;
            CP_ASYNC16(tb + off,       Ahi + gi);
            CP_ASYNC16(tb + PLB + off, Alo + gi);
        }
        #pragma unroll
        for (int i = tid; i < 512; i += 256) {           // B planes
            const int row = i >> 2, col = (i & 3) * 8;
            const uint32_t off = (uint32_t)(row * ASTRIDE + col) * 2;
            const size_t gi = (size_t)(bn + row) * K + k0 + col;
            CP_ASYNC16(tb + 2 * PLB + off, Bhi + gi);
            CP_ASYNC16(tb + 3 * PLB + off, Blo + gi);
        }
        CP_COMMIT();
    };

    const int NCH = K / BK;
    load_chunk(0, 0);

    for (int c = 0; c < NCH; c++) {
        const int st = c & 1;
        if (c + 1 < NCH) { load_chunk(st ^ 1, c + 1); CP_WAIT(1); }
        else             { CP_WAIT(0); }
        __syncthreads();

        const uint32_t tb = sb + st * STAGE_B;
        #pragma unroll
        for (int ks = 0; ks < 2; ks++) {
            const int kc = ks * 16 + lcol8;
            uint32_t ah[4][4], al[4][4];
            #pragma unroll
            for (int mf = 0; mf < 4; mf++) {
                const uint32_t addr = tb + (uint32_t)((wm + mf * 16 + lrow) * ASTRIDE + kc) * 2;
                ldsm_x4(ah[mf], addr);
                ldsm_x4(al[mf], addr + PLB);
            }
            uint32_t bh[2][4], bl[2][4];
            #pragma unroll
            for (int p = 0; p < 2; p++) {
                const uint32_t addr = tb + 2 * PLB
                    + (uint32_t)((wn + p * 16 + lrow) * ASTRIDE + kc) * 2;
                ldsm_x4(bh[p], addr);
                ldsm_x4(bl[p], addr + PLB);
            }
            #pragma unroll
            for (int mf = 0; mf < 4; mf++)
                #pragma unroll
                for (int nf = 0; nf < 4; nf++) {
                    const int p = nf >> 1, s = nf & 1;
                    mma_bf16(acc[mf][nf], ah[mf][0], ah[mf][1], ah[mf][2], ah[mf][3],
                             bl[p][s], bl[p][s + 2]);
                    mma_bf16(acc[mf][nf], al[mf][0], al[mf][1], al[mf][2], al[mf][3],
                             bh[p][s], bh[p][s + 2]);
                    mma_bf16(acc[mf][nf], ah[mf][0], ah[mf][1], ah[mf][2], ah[mf][3],
                             bh[p][s], bh[p][s + 2]);
                }
        }
        __syncthreads();
    }

    #pragma unroll
    for (int mf = 0; mf < 4; mf++)
        #pragma unroll
        for (int nf = 0; nf < 4; nf++) {
            const int r0 = bm + wm + mf * 16 + g;
            const int c0 = bn + wn + nf * 8 + tig * 2;
            *(float2*)(C + (size_t)r0 * N + c0)       = make_float2(acc[mf][nf][0], acc[mf][nf][1]);
            *(float2*)(C + (size_t)(r0 + 8) * N + c0) = make_float2(acc[mf][nf][2], acc[mf][nf][3]);
        }
}

// ---------------------------------------------------------------------------
// RoPE table
// ---------------------------------------------------------------------------
__global__ __launch_bounds__(128) void rope_table_kernel(const int* __restrict__ positions)
{
    const int t = blockIdx.x;
    const int i = threadIdx.x;
    const int pos = positions[t];
    const double inv_freq = exp(-(double)i * (2.0 / (double)D_) * log(10000.0));
    const float ang = (float)((double)pos * inv_freq);
    float s, c;
    sincosf(ang, &s, &c);
    g_rope[t * 128 + i] = make_float2(c, s);
}

// ---------------------------------------------------------------------------
// RMSNorm + RoPE; writes packed bf16-split q/k/v for the attention kernel.
// ---------------------------------------------------------------------------
__global__ __launch_bounds__(128) void norm_rope_kernel(
    const float* __restrict__ qw, const float* __restrict__ kw)
{
    const int t = blockIdx.x;
    const int h = blockIdx.y;
    const int i = threadIdx.x;

    const float* base = g_qkv + (size_t)t * QKV_N_ + h * D_;
    const float q0 = base[i],            q1 = base[i + 128];
    const float k0 = base[HID_ + i],     k1 = base[HID_ + i + 128];
    const float v0 = base[2*HID_ + i],   v1 = base[2*HID_ + i + 128];

    float sq = q0*q0 + q1*q1;
    float sk = k0*k0 + k1*k1;
    float sv = v0*v0 + v1*v1;

    __shared__ float redq[4], redk[4], redv[4];
    #pragma unroll
    for (int off = 16; off > 0; off >>= 1) {
        sq += __shfl_xor_sync(0xffffffff, sq, off);
        sk += __shfl_xor_sync(0xffffffff, sk, off);
        sv += __shfl_xor_sync(0xffffffff, sv, off);
    }
    const int warp = i >> 5, lane = i & 31;
    if (lane == 0) { redq[warp] = sq; redk[warp] = sk; redv[warp] = sv; }
    __syncthreads();
    sq = redq[0] + redq[1] + redq[2] + redq[3];
    sk = redk[0] + redk[1] + redk[2] + redk[3];
    sv = redv[0] + redv[1] + redv[2] + redv[3];

    const float rq = rsqrtf(sq * (1.f / D_) + EPS_);
    const float rk = rsqrtf(sk * (1.f / D_) + EPS_);
    const float rv = rsqrtf(sv * (1.f / D_) + EPS_);

    const float qn0 = q0 * rq * qw[i], qn1 = q1 * rq * qw[i + 128];
    const float kn0 = k0 * rk * kw[i], kn1 = k1 * rk * kw[i + 128];

    const float2 cs = g_rope[t * 128 + i];
    const float c = cs.x, s = cs.y;

    uint32_t* qo = g_q32 + ((size_t)h * T_ + t) * D_;
    uint32_t* ko = g_k32 + ((size_t)h * T_ + t) * D_;
    uint32_t* vo = g_v32 + ((size_t)h * T_ + t) * D_;

    qo[i]       = pack_split(qn0 * c - qn1 * s);
    qo[i + 128] = pack_split(qn1 * c + qn0 * s);
    ko[i]       = pack_split(kn0 * c - kn1 * s);
    ko[i + 128] = pack_split(kn1 * c + kn0 * s);
    vo[i]       = pack_split(v0 * rv);
    vo[i + 128] = pack_split(v1 * rv);
}

// ---------------------------------------------------------------------------
// Tensor-core flash attention (legacy mma path), bf16-split.
// Grid (T/32, NH), 256 threads. Emits bf16 hi/lo planes for the O-proj GEMM.
// ---------------------------------------------------------------------------
#define QSTRIDE 260
#define SSTRIDE 36
#define OFF_Q   0
#define OFF_K   (32 * QSTRIDE)
#define OFF_V   (OFF_K + 2 * 32 * QSTRIDE)
#define OFF_S   (OFF_V + 2 * 32 * QSTRIDE)
#define OFF_M   (OFF_S + 32 * SSTRIDE)
#define OFF_L   (OFF_M + 32)
#define OFF_A   (OFF_L + 32)
#define ATTN_SMEM_BYTES ((OFF_A + 32) * 4)

__global__ __launch_bounds__(256) void attn_kernel()
{
    extern __shared__ uint32_t sm[];
    uint32_t* Qs = sm + OFF_Q;
    uint32_t* Ks = sm + OFF_K;
    uint32_t* Vs = sm + OFF_V;
    float*    Ss = (float*)(sm + OFF_S);
    float*    mS = (float*)(sm + OFF_M);
    float*    lS = (float*)(sm + OFF_L);
    float*    aS = (float*)(sm + OFF_A);

    const int bx = blockIdx.x;
    const int h  = blockIdx.y;
    const int q0 = bx * 32;
    const int ntiles = bx + 1;

    const int tid  = threadIdx.x;
    const int wid  = tid >> 5, lane = tid & 31;
    const int g    = lane >> 2;
    const int tig  = lane & 3;

    {
        const uint32_t* qsrc = g_q32 + ((size_t)h * T_ + q0) * D_;
        #pragma unroll
        for (int i = tid; i < 2048; i += 256) {
            int r = i >> 6, c = (i & 63) * 4;
            uint32_t dst = (uint32_t)__cvta_generic_to_shared(&Qs[r * QSTRIDE + c]);
            CP_ASYNC16(dst, qsrc + (size_t)r * D_ + c);
        }
    }
    auto load_kv = [&](int buf, int t) {
        const size_t base = ((size_t)h * T_ + t * 32) * D_;
        uint32_t* kd = Ks + buf * 32 * QSTRIDE;
        uint32_t* vd = Vs + buf * 32 * QSTRIDE;
        #pragma unroll
        for (int i = tid; i < 2048; i += 256) {
            int r = i >> 6, c = (i & 63) * 4;
            uint32_t dk = (uint32_t)__cvta_generic_to_shared(&kd[r * QSTRIDE + c]);
            CP_ASYNC16(dk, g_k32 + base + (size_t)r * D_ + c);
            uint32_t dv = (uint32_t)__cvta_generic_to_shared(&vd[r * QSTRIDE + c]);
            CP_ASYNC16(dv, g_v32 + base + (size_t)r * D_ + c);
        }
        CP_COMMIT();
    };
    load_kv(0, 0);

    if (tid < 32) { mS[tid] = -1e30f; lS[tid] = 0.f; }

    float oc[8][4];
    #pragma unroll
    for (int nf = 0; nf < 8; nf++)
        #pragma unroll
        for (int r = 0; r < 4; r++) oc[nf][r] = 0.f;

    const int wq = wid >> 2;
    const int wk = wid & 3;
    const int srow = tid >> 3;
    const int sl8  = tid & 7;

    for (int t = 0; t < ntiles; t++) {
        const int buf = t & 1;
        if (t + 1 < ntiles) { load_kv(buf ^ 1, t + 1); CP_WAIT(1); }
        else                { CP_WAIT(0); }
        __syncthreads();

        const uint32_t* Kb = Ks + buf * 32 * QSTRIDE;
        float c4[4] = {0.f, 0.f, 0.f, 0.f};
        #pragma unroll
        for (int ks = 0; ks < 16; ks++) {
            const int kc = ks * 16 + 2 * tig;
            uint2 ua0 = *(const uint2*)&Qs[(wq * 16 + g    ) * QSTRIDE + kc];
            uint2 ua1 = *(const uint2*)&Qs[(wq * 16 + g + 8) * QSTRIDE + kc];
            uint2 ua2 = *(const uint2*)&Qs[(wq * 16 + g    ) * QSTRIDE + kc + 8];
            uint2 ua3 = *(const uint2*)&Qs[(wq * 16 + g + 8) * QSTRIDE + kc + 8];
            uint32_t Ah0 = MAIN2(ua0.x, ua0.y), Al0 = RESID2(ua0.x, ua0.y);
            uint32_t Ah1 = MAIN2(ua1.x, ua1.y), Al1 = RESID2(ua1.x, ua1.y);
            uint32_t Ah2 = MAIN2(ua2.x, ua2.y), Al2 = RESID2(ua2.x, ua2.y);
            uint32_t Ah3 = MAIN2(ua3.x, ua3.y), Al3 = RESID2(ua3.x, ua3.y);
            uint2 ub0 = *(const uint2*)&Kb[(wk * 8 + g) * QSTRIDE + kc];
            uint2 ub1 = *(const uint2*)&Kb[(wk * 8 + g) * QSTRIDE + kc + 8];
            uint32_t Bh0 = MAIN2(ub0.x, ub0.y), Bl0 = RESID2(ub0.x, ub0.y);
            uint32_t Bh1 = MAIN2(ub1.x, ub1.y), Bl1 = RESID2(ub1.x, ub1.y);
            mma_bf16(c4, Ah0, Ah1, Ah2, Ah3, Bl0, Bl1);
            mma_bf16(c4, Al0, Al1, Al2, Al3, Bh0, Bh1);
            mma_bf16(c4, Ah0, Ah1, Ah2, Ah3, Bh0, Bh1);
        }
        {
            const int sc = wk * 8 + 2 * tig;
            Ss[(wq * 16 + g    ) * SSTRIDE + sc    ] = c4[0];
            Ss[(wq * 16 + g    ) * SSTRIDE + sc + 1] = c4[1];
            Ss[(wq * 16 + g + 8) * SSTRIDE + sc    ] = c4[2];
            Ss[(wq * 16 + g + 8) * SSTRIDE + sc + 1] = c4[3];
        }
        __syncthreads();

        {
            const int c0 = sl8 * 4;
            float4 sv = *(const float4*)&Ss[srow * SSTRIDE + c0];
            const bool lastmask = (t == bx);
            float s0 = sv.x, s1 = sv.y, s2 = sv.z, s3 = sv.w;
            bool v0 = !lastmask || (c0 + 0 <= srow);
            bool v1 = !lastmask || (c0 + 1 <= srow);
            bool v2 = !lastmask || (c0 + 2 <= srow);
            bool v3 = !lastmask || (c0 + 3 <= srow);
            float lmax = -1e30f;
            if (v0) lmax = fmaxf(lmax, s0);
            if (v1) lmax = fmaxf(lmax, s1);
            if (v2) lmax = fmaxf(lmax, s2);
            if (v3) lmax = fmaxf(lmax, s3);
            #pragma unroll
            for (int off = 4; off > 0; off >>= 1)
                lmax = fmaxf(lmax, __shfl_xor_sync(0xffffffff, lmax, off, 8));
            const float m_old = mS[srow];
            const float mnew  = fmaxf(m_old, lmax);
            float p0 = v0 ? __expf(s0 - mnew) : 0.f;
            float p1 = v1 ? __expf(s1 - mnew) : 0.f;
            float p2 = v2 ? __expf(s2 - mnew) : 0.f;
            float p3 = v3 ? __expf(s3 - mnew) : 0.f;
            float lsum = p0 + p1 + p2 + p3;
            #pragma unroll
            for (int off = 4; off > 0; off >>= 1)
                lsum += __shfl_xor_sync(0xffffffff, lsum, off, 8);
            uint32_t* Pp = (uint32_t*)&Ss[srow * SSTRIDE + c0];
            Pp[0] = pack_split(p0); Pp[1] = pack_split(p1);
            Pp[2] = pack_split(p2); Pp[3] = pack_split(p3);
            if (sl8 == 0) {
                const float alpha = __expf(m_old - mnew);
                mS[srow] = mnew;
                lS[srow] = lS[srow] * alpha + lsum;
                aS[srow] = alpha;
            }
        }
        __syncthreads();

        {
            const int wq2 = wid >> 2, wd = wid & 3;
            const float a_lo = aS[wq2 * 16 + g];
            const float a_hi = aS[wq2 * 16 + g + 8];
            #pragma unroll
            for (int nf = 0; nf < 8; nf++) {
                oc[nf][0] *= a_lo; oc[nf][1] *= a_lo;
                oc[nf][2] *= a_hi; oc[nf][3] *= a_hi;
            }
            const uint32_t* Vb = Vs + buf * 32 * QSTRIDE;
            const uint32_t* Pu = (const uint32_t*)Ss;
            #pragma unroll
            for (int ks = 0; ks < 2; ks++) {
                const int kc = ks * 16 + 2 * tig;
                uint2 up0 = *(const uint2*)&Pu[(wq2 * 16 + g    ) * SSTRIDE + kc];
                uint2 up1 = *(const uint2*)&Pu[(wq2 * 16 + g + 8) * SSTRIDE + kc];
                uint2 up2 = *(const uint2*)&Pu[(wq2 * 16 + g    ) * SSTRIDE + kc + 8];
                uint2 up3 = *(const uint2*)&Pu[(wq2 * 16 + g + 8) * SSTRIDE + kc + 8];
                uint32_t Ah0 = MAIN2(up0.x, up0.y), Al0 = RESID2(up0.x, up0.y);
                uint32_t Ah1 = MAIN2(up1.x, up1.y), Al1 = RESID2(up1.x, up1.y);
                uint32_t Ah2 = MAIN2(up2.x, up2.y), Al2 = RESID2(up2.x, up2.y);
                uint32_t Ah3 = MAIN2(up3.x, up3.y), Al3 = RESID2(up3.x, up3.y);
                #pragma unroll
                for (int nf = 0; nf < 8; nf++) {
                    const int n0 = wd * 64 + nf * 8 + g;
                    uint32_t v0 = Vb[(kc    ) * QSTRIDE + n0];
                    uint32_t v1 = Vb[(kc + 1) * QSTRIDE + n0];
                    uint32_t v2 = Vb[(kc + 8) * QSTRIDE + n0];
                    uint32_t v3 = Vb[(kc + 9) * QSTRIDE + n0];
                    uint32_t Bh0 = MAIN2(v0, v1), Bl0 = RESID2(v0, v1);
                    uint32_t Bh1 = MAIN2(v2, v3), Bl1 = RESID2(v2, v3);
                    mma_bf16(oc[nf], Ah0, Ah1, Ah2, Ah3, Bl0, Bl1);
                    mma_bf16(oc[nf], Al0, Al1, Al2, Al3, Bh0, Bh1);
                    mma_bf16(oc[nf], Ah0, Ah1, Ah2, Ah3, Bh0, Bh1);
                }
            }
        }
        __syncthreads();
    }

    // finalize: O / l, split into hi/lo planes
    {
        const int wq2 = wid >> 2, wd = wid & 3;
        const float inv_lo = 1.f / lS[wq2 * 16 + g];
        const float inv_hi = 1.f / lS[wq2 * 16 + g + 8];
        const int r_lo = q0 + wq2 * 16 + g;
        const int r_hi = r_lo + 8;
        #pragma unroll
        for (int nf = 0; nf < 8; nf++) {
            const int n = h * D_ + wd * 64 + nf * 8 + 2 * tig;
            __nv_bfloat16 h0,l0,h1,l1,h2,l2,h3,l3;
            split_bf16(oc[nf][0] * inv_lo, h0, l0);
            split_bf16(oc[nf][1] * inv_lo, h1, l1);
            split_bf16(oc[nf][2] * inv_hi, h2, l2);
            split_bf16(oc[nf][3] * inv_hi, h3, l3);
            *(__nv_bfloat162*)&g_attnhi[(size_t)r_lo * HID_ + n] = __nv_bfloat162(h0, h1);
            *(__nv_bfloat162*)&g_attnlo[(size_t)r_lo * HID_ + n] = __nv_bfloat162(l0, l1);
            *(__nv_bfloat162*)&g_attnhi[(size_t)r_hi * HID_ + n] = __nv_bfloat162(h2, h3);
            *(__nv_bfloat162*)&g_attnlo[(size_t)r_hi * HID_ + n] = __nv_bfloat162(l2, l3);
        }
    }
}

// ---------------------------------------------------------------------------
// Launch
// ---------------------------------------------------------------------------
extern "C" void kernel_launch(void* const* d_in, const int* in_sizes, int n_in,
                              void* d_out, int out_size)
{
    const float* hidden    = (const float*)d_in[0];
    const int*   positions = (const int*)  d_in[1];
    const float* w_qkv     = (const float*)d_in[2];
    const float* w_o       = (const float*)d_in[3];
    const float* q_norm_w  = (const float*)d_in[4];
    const float* k_norm_w  = (const float*)d_in[5];
    float* out = (float*)d_out;

    float *qkv_ptr = nullptr;
    __nv_bfloat16 *hidhi, *hidlo, *wqhi, *wqlo, *wohi, *wolo, *athi, *atlo;
    cudaGetSymbolAddress((void**)&qkv_ptr, g_qkv);
    cudaGetSymbolAddress((void**)&hidhi, g_hidhi);
    cudaGetSymbolAddress((void**)&hidlo, g_hidlo);
    cudaGetSymbolAddress((void**)&wqhi,  g_wqkvThi);
    cudaGetSymbolAddress((void**)&wqlo,  g_wqkvTlo);
    cudaGetSymbolAddress((void**)&wohi,  g_woThi);
    cudaGetSymbolAddress((void**)&wolo,  g_woTlo);
    cudaGetSymbolAddress((void**)&athi,  g_attnhi);
    cudaGetSymbolAddress((void**)&atlo,  g_attnlo);

    cudaFuncSetAttribute(attn_kernel, cudaFuncAttributeMaxDynamicSharedMemorySize,
                         ATTN_SMEM_BYTES);
    cudaFuncSetAttribute(gemm_lds, cudaFuncAttributeMaxDynamicSharedMemorySize,
                         GEMM_SMEM);

    // Pre-pass: split/transpose operands into bf16 hi/lo planes
    split_planes<<<2048, 256>>>(hidden, hidhi, hidlo, (T_ * HID_) / 4);
    transpose_split<<<dim3(QKV_N_ / 32, HID_ / 32), 256>>>(w_qkv, wqhi, wqlo, HID_, QKV_N_);
    transpose_split<<<dim3(HID_ / 32, HID_ / 32), 256>>>(w_o, wohi, wolo, HID_, HID_);
    rope_table_kernel<<<T_, 128>>>(positions);

    // 1) QKV projection
    gemm_lds<<<dim3(T_ / 128, QKV_N_ / 128), 256, GEMM_SMEM>>>(
        hidhi, hidlo, wqhi, wqlo, qkv_ptr, T_, QKV_N_, HID_);

    // 2) RMSNorm + RoPE
    norm_rope_kernel<<<dim3(T_, NH_), 128>>>(q_norm_w, k_norm_w);

    // 3) Flash attention
    attn_kernel<<<dim3(T_ / 32, NH_), 256, ATTN_SMEM_BYTES>>>();

    // 4) Output projection
    gemm_lds<<<dim3(T_ / 128, HID_ / 128), 256, GEMM_SMEM>>>(
        athi, atlo, wohi, wolo, out, T_, HID_, HID_);
}

// round 11
// speedup vs baseline: 1.4539x; 1.4539x over previous
#include <cuda_runtime.h>
#include <cuda_bf16.h>
#include <math.h>
#include <stdint.h>

// Problem constants
#define T_   2048
#define HID_ 4096
#define NH_  16
#define D_   256
#define QKV_N_ (3 * HID_)   // 12288
#define EPS_ 1e-6f

// ---------------------------------------------------------------------------
// Scratch (device globals — no allocation allowed)
// ---------------------------------------------------------------------------
__device__ float    g_qkv [T_ * QKV_N_];      // fp32 qkv projection
__device__ float    g_attn[T_ * HID_];        // fp32 attention output
// int8 two-digit operands
__device__ char     g_ad1[T_ * HID_],      g_ad0[T_ * HID_];       // hidden
__device__ char     g_wq1[QKV_N_ * HID_],  g_wq0[QKV_N_ * HID_];   // w_qkv^T [N][K]
__device__ char     g_wo1[HID_ * HID_],    g_wo0[HID_ * HID_];     // w_o^T   [N][K]
__device__ char     g_cd1[T_ * HID_],      g_cd0[T_ * HID_];       // attn out
__device__ float    g_as[T_], g_cs[T_];                            // row scales
__device__ float    g_bs1[QKV_N_], g_bs2[HID_];                    // col scales
__device__ unsigned g_cmax1[QKV_N_], g_cmax2[HID_];                // col |max| bits
// attention inputs (packed bf16 hi/lo: (lo16<<16)|hi16)
__device__ uint32_t g_q32[NH_ * T_ * D_];
__device__ uint32_t g_k32[NH_ * T_ * D_];
__device__ uint32_t g_v32[NH_ * T_ * D_];
__device__ float2   g_rope[T_ * (D_ / 2)];

// ---------------------------------------------------------------------------
// Common helpers
// ---------------------------------------------------------------------------
__device__ __forceinline__ void split_bf16(float v, __nv_bfloat16& h, __nv_bfloat16& l) {
    h = __float2bfloat16(v);
    l = __float2bfloat16(v - __bfloat162float(h));
}
__device__ __forceinline__ uint32_t pack_split(float x) {
    __nv_bfloat16 hb, lb; split_bf16(x, hb, lb);
    return ((uint32_t)__bfloat16_as_ushort(lb) << 16) | (uint32_t)__bfloat16_as_ushort(hb);
}
#define MAIN2(u0, u1)  __byte_perm((u0), (u1), 0x5410)
#define RESID2(u0, u1) __byte_perm((u0), (u1), 0x7632)

__device__ __forceinline__ void mma_bf16(float c[4],
                                         uint32_t a0, uint32_t a1, uint32_t a2, uint32_t a3,
                                         uint32_t b0, uint32_t b1) {
    asm volatile(
        "mma.sync.aligned.m16n8k16.row.col.f32.bf16.bf16.f32 "
        "{%0,%1,%2,%3}, {%4,%5,%6,%7}, {%8,%9}, {%0,%1,%2,%3};"
        : "+f"(c[0]), "+f"(c[1]), "+f"(c[2]), "+f"(c[3])
        : "r"(a0), "r"(a1), "r"(a2), "r"(a3), "r"(b0), "r"(b1));
}

__device__ __forceinline__ void mma_s8(int c[4],
                                       uint32_t a0, uint32_t a1, uint32_t a2, uint32_t a3,
                                       uint32_t b0, uint32_t b1) {
    asm volatile(
        "mma.sync.aligned.m16n8k32.row.col.s32.s8.s8.s32 "
        "{%0,%1,%2,%3}, {%4,%5,%6,%7}, {%8,%9}, {%0,%1,%2,%3};"
        : "+r"(c[0]), "+r"(c[1]), "+r"(c[2]), "+r"(c[3])
        : "r"(a0), "r"(a1), "r"(a2), "r"(a3), "r"(b0), "r"(b1));
}

#define CP_ASYNC16(smem_u32, gptr) \
    asm volatile("cp.async.cg.shared.global [%0], [%1], 16;" :: "r"(smem_u32), "l"(gptr))
#define CP_COMMIT() asm volatile("cp.async.commit_group;")
#define CP_WAIT(n)  asm volatile("cp.async.wait_group %0;" :: "n"(n))

// quantize helper: v -> (d1, d0) with q = d1*128 + d0, |q| <= 16256
__device__ __forceinline__ void quant2(float v, float inv, char& d1, char& d0) {
    int q  = __float2int_rn(v * inv);
    int q1 = (q + 64) >> 7;          // round-to-nearest high digit
    d1 = (char)q1;
    d0 = (char)(q - (q1 << 7));      // in [-64, 63]
}

// ---------------------------------------------------------------------------
// Row quantization: per-row |max| -> scale; write d1/d0 planes [M][K]
// ---------------------------------------------------------------------------
__global__ __launch_bounds__(256) void quant_rows(
    const float* __restrict__ src, char* __restrict__ d1p, char* __restrict__ d0p,
    float* __restrict__ scales, int K)
{
    const int m = blockIdx.x;
    const int t = threadIdx.x;
    const float4* row = (const float4*)(src + (size_t)m * K);
    const int K4 = K >> 2;

    float mx = 0.f;
    for (int i = t; i < K4; i += 256) {
        float4 v = row[i];
        mx = fmaxf(mx, fmaxf(fmaxf(fabsf(v.x), fabsf(v.y)), fmaxf(fabsf(v.z), fabsf(v.w))));
    }
    __shared__ float red[8];
    #pragma unroll
    for (int off = 16; off > 0; off >>= 1)
        mx = fmaxf(mx, __shfl_xor_sync(0xffffffff, mx, off));
    if ((t & 31) == 0) red[t >> 5] = mx;
    __syncthreads();
    mx = fmaxf(fmaxf(fmaxf(red[0], red[1]), fmaxf(red[2], red[3])),
               fmaxf(fmaxf(red[4], red[5]), fmaxf(red[6], red[7])));
    const float mxg = fmaxf(mx, 1e-20f);
    const float inv = 16256.f / mxg;
    if (t == 0) scales[m] = mxg / 16256.f;

    char4* o1 = (char4*)(d1p + (size_t)m * K);
    char4* o0 = (char4*)(d0p + (size_t)m * K);
    for (int i = t; i < K4; i += 256) {
        float4 v = row[i];
        char a1, a0, b1, b0, c1, c0, e1, e0;
        quant2(v.x, inv, a1, a0); quant2(v.y, inv, b1, b0);
        quant2(v.z, inv, c1, c0); quant2(v.w, inv, e1, e0);
        o1[i] = make_char4(a1, b1, c1, e1);
        o0[i] = make_char4(a0, b0, c0, e0);
    }
}

// ---------------------------------------------------------------------------
// Column |max| of w [K][N] via atomicMax on float bits (nonneg after fabs)
// ---------------------------------------------------------------------------
__global__ __launch_bounds__(256) void colmax_kernel(
    const float* __restrict__ w, unsigned* __restrict__ cmax, int segK, int N)
{
    const int n  = blockIdx.x * 256 + threadIdx.x;
    const int k0 = blockIdx.y * segK;
    float mx = 0.f;
    for (int k = k0; k < k0 + segK; k++)
        mx = fmaxf(mx, fabsf(w[(size_t)k * N + n]));
    atomicMax(cmax + n, __float_as_uint(mx));
}

// ---------------------------------------------------------------------------
// Transpose + quantize: w [K][N] fp32 -> d1/d0 [N][K] int8 with col scales
// ---------------------------------------------------------------------------
__global__ __launch_bounds__(256) void transpose_quant(
    const float* __restrict__ w, const unsigned* __restrict__ cmax,
    float* __restrict__ scales, char* __restrict__ d1p, char* __restrict__ d0p,
    int K, int N)
{
    __shared__ float tile[32][33];
    const int t  = threadIdx.x;
    const int tx = t & 31, ty = t >> 5;
    const int n0 = blockIdx.x * 32, k0 = blockIdx.y * 32;

    #pragma unroll
    for (int j = 0; j < 4; j++)
        tile[ty + j * 8][tx] = w[(size_t)(k0 + ty + j * 8) * N + n0 + tx];
    if (ty == 0 && blockIdx.y == 0)
        scales[n0 + tx] = fmaxf(__uint_as_float(cmax[n0 + tx]), 1e-20f) / 16256.f;
    __syncthreads();

    const int nin = t >> 3;          // 0..31
    const int kq  = (t & 7) * 4;     // 0..28
    const float inv = 16256.f / fmaxf(__uint_as_float(cmax[n0 + nin]), 1e-20f);
    char a1, a0, b1, b0, c1, c0, e1, e0;
    quant2(tile[kq + 0][nin], inv, a1, a0);
    quant2(tile[kq + 1][nin], inv, b1, b0);
    quant2(tile[kq + 2][nin], inv, c1, c0);
    quant2(tile[kq + 3][nin], inv, e1, e0);
    *(char4*)(d1p + (size_t)(n0 + nin) * K + k0 + kq) = make_char4(a1, b1, c1, e1);
    *(char4*)(d0p + (size_t)(n0 + nin) * K + k0 + kq) = make_char4(a0, b0, c0, e0);
}

// ---------------------------------------------------------------------------
// int8 two-digit GEMM: C_fp32[M,N] = (sa*sb) * qA[M,K] @ qB[N,K]^T
// 128x128 tile, BK=64, 512 threads (16 warps, 4x4 of 32x32), 2-stage cp.async.
// 3 IMMA.16832 per k32 step (d1d1 -> P1; d1d0 + d0d1 -> Pc; d0d0 dropped).
// ---------------------------------------------------------------------------
#define ISTRIDE 80
#define IPL     (128 * ISTRIDE)     // 10240 bytes per digit plane
#define ISTAGE  (4 * IPL)           // 40960
#define IGEMM_SMEM (2 * ISTAGE)     // 81920

__global__ __launch_bounds__(512) void gemm_i8(
    const char* __restrict__ Ad1, const char* __restrict__ Ad0,
    const char* __restrict__ Bd1, const char* __restrict__ Bd0,
    const float* __restrict__ sa, const float* __restrict__ sb,
    float* __restrict__ C, int M, int N, int K)
{
    extern __shared__ char ism[];
    const uint32_t smb = (uint32_t)__cvta_generic_to_shared(ism);

    const int tid  = threadIdx.x;
    const int wid  = tid >> 5, lane = tid & 31;
    const int bm   = blockIdx.y * 128;
    const int bn   = blockIdx.x * 128;
    const int wm   = (wid >> 2) * 32;
    const int wn   = (wid & 3)  * 32;
    const int g    = lane >> 2;
    const int tig  = lane & 3;

    int P1[2][4][4], Pc[2][4][4];
    #pragma unroll
    for (int mf = 0; mf < 2; mf++)
        #pragma unroll
        for (int nf = 0; nf < 4; nf++)
            #pragma unroll
            for (int r = 0; r < 4; r++) { P1[mf][nf][r] = 0; Pc[mf][nf][r] = 0; }

    // loaders: each plane = 128 rows x 64B = 512 x 16B; 512 threads -> 1 each
    const int lr = tid >> 2;             // row 0..127
    const int lc = (tid & 3) * 16;       // 0,16,32,48
    auto load_chunk = [&](int stg, int c) {
        const int k0 = c * 64;
        const uint32_t tb = smb + stg * ISTAGE;
        const uint32_t off = (uint32_t)(lr * ISTRIDE + lc);
        const size_t ga = (size_t)(bm + lr) * K + k0 + lc;
        const size_t gb = (size_t)(bn + lr) * K + k0 + lc;
        CP_ASYNC16(tb + 0 * IPL + off, Ad1 + ga);
        CP_ASYNC16(tb + 1 * IPL + off, Ad0 + ga);
        CP_ASYNC16(tb + 2 * IPL + off, Bd1 + gb);
        CP_ASYNC16(tb + 3 * IPL + off, Bd0 + gb);
        CP_COMMIT();
    };

    const int NCH = K / 64;
    load_chunk(0, 0);

    for (int c = 0; c < NCH; c++) {
        const int st = c & 1;
        if (c + 1 < NCH) { load_chunk(st ^ 1, c + 1); CP_WAIT(1); }
        else             { CP_WAIT(0); }
        __syncthreads();

        const char* tb = ism + st * ISTAGE;
        #pragma unroll
        for (int s = 0; s < 2; s++) {
            const int kc = s * 32 + 4 * tig;
            uint32_t a1[2][4], a0[2][4];
            #pragma unroll
            for (int mf = 0; mf < 2; mf++) {
                const int ro = (wm + mf * 16 + g) * ISTRIDE + kc;
                a1[mf][0] = *(const uint32_t*)(tb + ro);
                a1[mf][1] = *(const uint32_t*)(tb + ro + 8 * ISTRIDE);
                a1[mf][2] = *(const uint32_t*)(tb + ro + 16);
                a1[mf][3] = *(const uint32_t*)(tb + ro + 8 * ISTRIDE + 16);
                a0[mf][0] = *(const uint32_t*)(tb + IPL + ro);
                a0[mf][1] = *(const uint32_t*)(tb + IPL + ro + 8 * ISTRIDE);
                a0[mf][2] = *(const uint32_t*)(tb + IPL + ro + 16);
                a0[mf][3] = *(const uint32_t*)(tb + IPL + ro + 8 * ISTRIDE + 16);
            }
            #pragma unroll
            for (int nf = 0; nf < 4; nf++) {
                const int co = (wn + nf * 8 + g) * ISTRIDE + kc;
                uint32_t b1_0 = *(const uint32_t*)(tb + 2 * IPL + co);
                uint32_t b1_1 = *(const uint32_t*)(tb + 2 * IPL + co + 16);
                uint32_t b0_0 = *(const uint32_t*)(tb + 3 * IPL + co);
                uint32_t b0_1 = *(const uint32_t*)(tb + 3 * IPL + co + 16);
                #pragma unroll
                for (int mf = 0; mf < 2; mf++) {
                    mma_s8(P1[mf][nf], a1[mf][0], a1[mf][1], a1[mf][2], a1[mf][3], b1_0, b1_1);
                    mma_s8(Pc[mf][nf], a1[mf][0], a1[mf][1], a1[mf][2], a1[mf][3], b0_0, b0_1);
                    mma_s8(Pc[mf][nf], a0[mf][0], a0[mf][1], a0[mf][2], a0[mf][3], b1_0, b1_1);
                }
            }
        }
        __syncthreads();
    }

    // epilogue: C = sa*sb*(16384*P1 + 128*Pc)
    #pragma unroll
    for (int mf = 0; mf < 2; mf++) {
        const int r0 = bm + wm + mf * 16 + g;
        const float sr0 = sa[r0], sr8 = sa[r0 + 8];
        #pragma unroll
        for (int nf = 0; nf < 4; nf++) {
            const int c0 = bn + wn + nf * 8 + 2 * tig;
            const float sc0 = sb[c0], sc1 = sb[c0 + 1];
            float v0 = sr0 * sc0 * fmaf(16384.f, (float)P1[mf][nf][0], 128.f * (float)Pc[mf][nf][0]);
            float v1 = sr0 * sc1 * fmaf(16384.f, (float)P1[mf][nf][1], 128.f * (float)Pc[mf][nf][1]);
            float v2 = sr8 * sc0 * fmaf(16384.f, (float)P1[mf][nf][2], 128.f * (float)Pc[mf][nf][2]);
            float v3 = sr8 * sc1 * fmaf(16384.f, (float)P1[mf][nf][3], 128.f * (float)Pc[mf][nf][3]);
            *(float2*)(C + (size_t)r0 * N + c0)       = make_float2(v0, v1);
            *(float2*)(C + (size_t)(r0 + 8) * N + c0) = make_float2(v2, v3);
        }
    }
}

// ---------------------------------------------------------------------------
// RoPE table
// ---------------------------------------------------------------------------
__global__ __launch_bounds__(128) void rope_table_kernel(const int* __restrict__ positions)
{
    const int t = blockIdx.x;
    const int i = threadIdx.x;
    const int pos = positions[t];
    const double inv_freq = exp(-(double)i * (2.0 / (double)D_) * log(10000.0));
    const float ang = (float)((double)pos * inv_freq);
    float s, c;
    sincosf(ang, &s, &c);
    g_rope[t * 128 + i] = make_float2(c, s);
}

// ---------------------------------------------------------------------------
// RMSNorm + RoPE; writes packed bf16-split q/k/v for the attention kernel.
// ---------------------------------------------------------------------------
__global__ __launch_bounds__(128) void norm_rope_kernel(
    const float* __restrict__ qw, const float* __restrict__ kw)
{
    const int t = blockIdx.x;
    const int h = blockIdx.y;
    const int i = threadIdx.x;

    const float* base = g_qkv + (size_t)t * QKV_N_ + h * D_;
    const float q0 = base[i],            q1 = base[i + 128];
    const float k0 = base[HID_ + i],     k1 = base[HID_ + i + 128];
    const float v0 = base[2*HID_ + i],   v1 = base[2*HID_ + i + 128];

    float sq = q0*q0 + q1*q1;
    float sk = k0*k0 + k1*k1;
    float sv = v0*v0 + v1*v1;

    __shared__ float redq[4], redk[4], redv[4];
    #pragma unroll
    for (int off = 16; off > 0; off >>= 1) {
        sq += __shfl_xor_sync(0xffffffff, sq, off);
        sk += __shfl_xor_sync(0xffffffff, sk, off);
        sv += __shfl_xor_sync(0xffffffff, sv, off);
    }
    const int warp = i >> 5, lane = i & 31;
    if (lane == 0) { redq[warp] = sq; redk[warp] = sk; redv[warp] = sv; }
    __syncthreads();
    sq = redq[0] + redq[1] + redq[2] + redq[3];
    sk = redk[0] + redk[1] + redk[2] + redk[3];
    sv = redv[0] + redv[1] + redv[2] + redv[3];

    const float rq = rsqrtf(sq * (1.f / D_) + EPS_);
    const float rk = rsqrtf(sk * (1.f / D_) + EPS_);
    const float rv = rsqrtf(sv * (1.f / D_) + EPS_);

    const float qn0 = q0 * rq * qw[i], qn1 = q1 * rq * qw[i + 128];
    const float kn0 = k0 * rk * kw[i], kn1 = k1 * rk * kw[i + 128];

    const float2 cs = g_rope[t * 128 + i];
    const float c = cs.x, s = cs.y;

    uint32_t* qo = g_q32 + ((size_t)h * T_ + t) * D_;
    uint32_t* ko = g_k32 + ((size_t)h * T_ + t) * D_;
    uint32_t* vo = g_v32 + ((size_t)h * T_ + t) * D_;

    qo[i]       = pack_split(qn0 * c - qn1 * s);
    qo[i + 128] = pack_split(qn1 * c + qn0 * s);
    ko[i]       = pack_split(kn0 * c - kn1 * s);
    ko[i + 128] = pack_split(kn1 * c + kn0 * s);
    vo[i]       = pack_split(v0 * rv);
    vo[i + 128] = pack_split(v1 * rv);
}

// ---------------------------------------------------------------------------
// Tensor-core flash attention (R4-proven), bf16-split; emits fp32 g_attn.
// Grid (T/32, NH), 256 threads.
// ---------------------------------------------------------------------------
#define QSTRIDE 260
#define SSTRIDE 36
#define OFF_Q   0
#define OFF_K   (32 * QSTRIDE)
#define OFF_V   (OFF_K + 2 * 32 * QSTRIDE)
#define OFF_S   (OFF_V + 2 * 32 * QSTRIDE)
#define OFF_M   (OFF_S + 32 * SSTRIDE)
#define OFF_L   (OFF_M + 32)
#define OFF_A   (OFF_L + 32)
#define ATTN_SMEM_BYTES ((OFF_A + 32) * 4)

__global__ __launch_bounds__(256) void attn_kernel()
{
    extern __shared__ uint32_t sm[];
    uint32_t* Qs = sm + OFF_Q;
    uint32_t* Ks = sm + OFF_K;
    uint32_t* Vs = sm + OFF_V;
    float*    Ss = (float*)(sm + OFF_S);
    float*    mS = (float*)(sm + OFF_M);
    float*    lS = (float*)(sm + OFF_L);
    float*    aS = (float*)(sm + OFF_A);

    const int bx = blockIdx.x;
    const int h  = blockIdx.y;
    const int q0 = bx * 32;
    const int ntiles = bx + 1;

    const int tid  = threadIdx.x;
    const int wid  = tid >> 5, lane = tid & 31;
    const int g    = lane >> 2;
    const int tig  = lane & 3;

    {
        const uint32_t* qsrc = g_q32 + ((size_t)h * T_ + q0) * D_;
        #pragma unroll
        for (int i = tid; i < 2048; i += 256) {
            int r = i >> 6, c = (i & 63) * 4;
            uint32_t dst = (uint32_t)__cvta_generic_to_shared(&Qs[r * QSTRIDE + c]);
            CP_ASYNC16(dst, qsrc + (size_t)r * D_ + c);
        }
    }
    auto load_kv = [&](int buf, int t) {
        const size_t base = ((size_t)h * T_ + t * 32) * D_;
        uint32_t* kd = Ks + buf * 32 * QSTRIDE;
        uint32_t* vd = Vs + buf * 32 * QSTRIDE;
        #pragma unroll
        for (int i = tid; i < 2048; i += 256) {
            int r = i >> 6, c = (i & 63) * 4;
            uint32_t dk = (uint32_t)__cvta_generic_to_shared(&kd[r * QSTRIDE + c]);
            CP_ASYNC16(dk, g_k32 + base + (size_t)r * D_ + c);
            uint32_t dv = (uint32_t)__cvta_generic_to_shared(&vd[r * QSTRIDE + c]);
            CP_ASYNC16(dv, g_v32 + base + (size_t)r * D_ + c);
        }
        CP_COMMIT();
    };
    load_kv(0, 0);

    if (tid < 32) { mS[tid] = -1e30f; lS[tid] = 0.f; }

    float oc[8][4];
    #pragma unroll
    for (int nf = 0; nf < 8; nf++)
        #pragma unroll
        for (int r = 0; r < 4; r++) oc[nf][r] = 0.f;

    const int wq = wid >> 2;
    const int wk = wid & 3;
    const int srow = tid >> 3;
    const int sl8  = tid & 7;

    for (int t = 0; t < ntiles; t++) {
        const int buf = t & 1;
        if (t + 1 < ntiles) { load_kv(buf ^ 1, t + 1); CP_WAIT(1); }
        else                { CP_WAIT(0); }
        __syncthreads();

        const uint32_t* Kb = Ks + buf * 32 * QSTRIDE;
        float c4[4] = {0.f, 0.f, 0.f, 0.f};
        #pragma unroll
        for (int ks = 0; ks < 16; ks++) {
            const int kc = ks * 16 + 2 * tig;
            uint2 ua0 = *(const uint2*)&Qs[(wq * 16 + g    ) * QSTRIDE + kc];
            uint2 ua1 = *(const uint2*)&Qs[(wq * 16 + g + 8) * QSTRIDE + kc];
            uint2 ua2 = *(const uint2*)&Qs[(wq * 16 + g    ) * QSTRIDE + kc + 8];
            uint2 ua3 = *(const uint2*)&Qs[(wq * 16 + g + 8) * QSTRIDE + kc + 8];
            uint32_t Ah0 = MAIN2(ua0.x, ua0.y), Al0 = RESID2(ua0.x, ua0.y);
            uint32_t Ah1 = MAIN2(ua1.x, ua1.y), Al1 = RESID2(ua1.x, ua1.y);
            uint32_t Ah2 = MAIN2(ua2.x, ua2.y), Al2 = RESID2(ua2.x, ua2.y);
            uint32_t Ah3 = MAIN2(ua3.x, ua3.y), Al3 = RESID2(ua3.x, ua3.y);
            uint2 ub0 = *(const uint2*)&Kb[(wk * 8 + g) * QSTRIDE + kc];
            uint2 ub1 = *(const uint2*)&Kb[(wk * 8 + g) * QSTRIDE + kc + 8];
            uint32_t Bh0 = MAIN2(ub0.x, ub0.y), Bl0 = RESID2(ub0.x, ub0.y);
            uint32_t Bh1 = MAIN2(ub1.x, ub1.y), Bl1 = RESID2(ub1.x, ub1.y);
            mma_bf16(c4, Ah0, Ah1, Ah2, Ah3, Bl0, Bl1);
            mma_bf16(c4, Al0, Al1, Al2, Al3, Bh0, Bh1);
            mma_bf16(c4, Ah0, Ah1, Ah2, Ah3, Bh0, Bh1);
        }
        {
            const int sc = wk * 8 + 2 * tig;
            Ss[(wq * 16 + g    ) * SSTRIDE + sc    ] = c4[0];
            Ss[(wq * 16 + g    ) * SSTRIDE + sc + 1] = c4[1];
            Ss[(wq * 16 + g + 8) * SSTRIDE + sc    ] = c4[2];
            Ss[(wq * 16 + g + 8) * SSTRIDE + sc + 1] = c4[3];
        }
        __syncthreads();

        {
            const int c0 = sl8 * 4;
            float4 sv = *(const float4*)&Ss[srow * SSTRIDE + c0];
            const bool lastmask = (t == bx);
            float s0 = sv.x, s1 = sv.y, s2 = sv.z, s3 = sv.w;
            bool v0 = !lastmask || (c0 + 0 <= srow);
            bool v1 = !lastmask || (c0 + 1 <= srow);
            bool v2 = !lastmask || (c0 + 2 <= srow);
            bool v3 = !lastmask || (c0 + 3 <= srow);
            float lmax = -1e30f;
            if (v0) lmax = fmaxf(lmax, s0);
            if (v1) lmax = fmaxf(lmax, s1);
            if (v2) lmax = fmaxf(lmax, s2);
            if (v3) lmax = fmaxf(lmax, s3);
            #pragma unroll
            for (int off = 4; off > 0; off >>= 1)
                lmax = fmaxf(lmax, __shfl_xor_sync(0xffffffff, lmax, off, 8));
            const float m_old = mS[srow];
            const float mnew  = fmaxf(m_old, lmax);
            float p0 = v0 ? __expf(s0 - mnew) : 0.f;
            float p1 = v1 ? __expf(s1 - mnew) : 0.f;
            float p2 = v2 ? __expf(s2 - mnew) : 0.f;
            float p3 = v3 ? __expf(s3 - mnew) : 0.f;
            float lsum = p0 + p1 + p2 + p3;
            #pragma unroll
            for (int off = 4; off > 0; off >>= 1)
                lsum += __shfl_xor_sync(0xffffffff, lsum, off, 8);
            uint32_t* Pp = (uint32_t*)&Ss[srow * SSTRIDE + c0];
            Pp[0] = pack_split(p0); Pp[1] = pack_split(p1);
            Pp[2] = pack_split(p2); Pp[3] = pack_split(p3);
            if (sl8 == 0) {
                const float alpha = __expf(m_old - mnew);
                mS[srow] = mnew;
                lS[srow] = lS[srow] * alpha + lsum;
                aS[srow] = alpha;
            }
        }
        __syncthreads();

        {
            const int wq2 = wid >> 2, wd = wid & 3;
            const float a_lo = aS[wq2 * 16 + g];
            const float a_hi = aS[wq2 * 16 + g + 8];
            #pragma unroll
            for (int nf = 0; nf < 8; nf++) {
                oc[nf][0] *= a_lo; oc[nf][1] *= a_lo;
                oc[nf][2] *= a_hi; oc[nf][3] *= a_hi;
            }
            const uint32_t* Vb = Vs + buf * 32 * QSTRIDE;
            const uint32_t* Pu = (const uint32_t*)Ss;
            #pragma unroll
            for (int ks = 0; ks < 2; ks++) {
                const int kc = ks * 16 + 2 * tig;
                uint2 up0 = *(const uint2*)&Pu[(wq2 * 16 + g    ) * SSTRIDE + kc];
                uint2 up1 = *(const uint2*)&Pu[(wq2 * 16 + g + 8) * SSTRIDE + kc];
                uint2 up2 = *(const uint2*)&Pu[(wq2 * 16 + g    ) * SSTRIDE + kc + 8];
                uint2 up3 = *(const uint2*)&Pu[(wq2 * 16 + g + 8) * SSTRIDE + kc + 8];
                uint32_t Ah0 = MAIN2(up0.x, up0.y), Al0 = RESID2(up0.x, up0.y);
                uint32_t Ah1 = MAIN2(up1.x, up1.y), Al1 = RESID2(up1.x, up1.y);
                uint32_t Ah2 = MAIN2(up2.x, up2.y), Al2 = RESID2(up2.x, up2.y);
                uint32_t Ah3 = MAIN2(up3.x, up3.y), Al3 = RESID2(up3.x, up3.y);
                #pragma unroll
                for (int nf = 0; nf < 8; nf++) {
                    const int n0 = wd * 64 + nf * 8 + g;
                    uint32_t v0 = Vb[(kc    ) * QSTRIDE + n0];
                    uint32_t v1 = Vb[(kc + 1) * QSTRIDE + n0];
                    uint32_t v2 = Vb[(kc + 8) * QSTRIDE + n0];
                    uint32_t v3 = Vb[(kc + 9) * QSTRIDE + n0];
                    uint32_t Bh0 = MAIN2(v0, v1), Bl0 = RESID2(v0, v1);
                    uint32_t Bh1 = MAIN2(v2, v3), Bl1 = RESID2(v2, v3);
                    mma_bf16(oc[nf], Ah0, Ah1, Ah2, Ah3, Bl0, Bl1);
                    mma_bf16(oc[nf], Al0, Al1, Al2, Al3, Bh0, Bh1);
                    mma_bf16(oc[nf], Ah0, Ah1, Ah2, Ah3, Bh0, Bh1);
                }
            }
        }
        __syncthreads();
    }

    // finalize: O / l -> fp32 g_attn
    {
        const int wq2 = wid >> 2, wd = wid & 3;
        const float inv_lo = 1.f / lS[wq2 * 16 + g];
        const float inv_hi = 1.f / lS[wq2 * 16 + g + 8];
        const int r_lo = q0 + wq2 * 16 + g;
        const int r_hi = r_lo + 8;
        #pragma unroll
        for (int nf = 0; nf < 8; nf++) {
            const int n = h * D_ + wd * 64 + nf * 8 + 2 * tig;
            *(float2*)&g_attn[(size_t)r_lo * HID_ + n] =
                make_float2(oc[nf][0] * inv_lo, oc[nf][1] * inv_lo);
            *(float2*)&g_attn[(size_t)r_hi * HID_ + n] =
                make_float2(oc[nf][2] * inv_hi, oc[nf][3] * inv_hi);
        }
    }
}

// ---------------------------------------------------------------------------
// Launch
// ---------------------------------------------------------------------------
extern "C" void kernel_launch(void* const* d_in, const int* in_sizes, int n_in,
                              void* d_out, int out_size)
{
    const float* hidden    = (const float*)d_in[0];
    const int*   positions = (const int*)  d_in[1];
    const float* w_qkv     = (const float*)d_in[2];
    const float* w_o       = (const float*)d_in[3];
    const float* q_norm_w  = (const float*)d_in[4];
    const float* k_norm_w  = (const float*)d_in[5];
    float* out = (float*)d_out;

    float *qkv_ptr, *attn_ptr, *as_p, *cs_p, *bs1_p, *bs2_p;
    char *ad1, *ad0, *wq1, *wq0, *wo1, *wo0, *cd1, *cd0;
    unsigned *cm1, *cm2;
    cudaGetSymbolAddress((void**)&qkv_ptr,  g_qkv);
    cudaGetSymbolAddress((void**)&attn_ptr, g_attn);
    cudaGetSymbolAddress((void**)&ad1, g_ad1);  cudaGetSymbolAddress((void**)&ad0, g_ad0);
    cudaGetSymbolAddress((void**)&wq1, g_wq1);  cudaGetSymbolAddress((void**)&wq0, g_wq0);
    cudaGetSymbolAddress((void**)&wo1, g_wo1);  cudaGetSymbolAddress((void**)&wo0, g_wo0);
    cudaGetSymbolAddress((void**)&cd1, g_cd1);  cudaGetSymbolAddress((void**)&cd0, g_cd0);
    cudaGetSymbolAddress((void**)&as_p, g_as);  cudaGetSymbolAddress((void**)&cs_p, g_cs);
    cudaGetSymbolAddress((void**)&bs1_p, g_bs1); cudaGetSymbolAddress((void**)&bs2_p, g_bs2);
    cudaGetSymbolAddress((void**)&cm1, g_cmax1); cudaGetSymbolAddress((void**)&cm2, g_cmax2);

    cudaFuncSetAttribute(attn_kernel, cudaFuncAttributeMaxDynamicSharedMemorySize,
                         ATTN_SMEM_BYTES);
    cudaFuncSetAttribute(gemm_i8, cudaFuncAttributeMaxDynamicSharedMemorySize,
                         IGEMM_SMEM);

    // Prepass: quantize activations + weights
    cudaMemsetAsync(cm1, 0, QKV_N_ * sizeof(unsigned));
    cudaMemsetAsync(cm2, 0, HID_ * sizeof(unsigned));
    quant_rows<<<T_, 256>>>(hidden, ad1, ad0, as_p, HID_);
    colmax_kernel<<<dim3(QKV_N_ / 256, 16), 256>>>(w_qkv, cm1, HID_ / 16, QKV_N_);
    transpose_quant<<<dim3(QKV_N_ / 32, HID_ / 32), 256>>>(w_qkv, cm1, bs1_p, wq1, wq0,
                                                           HID_, QKV_N_);
    colmax_kernel<<<dim3(HID_ / 256, 16), 256>>>(w_o, cm2, HID_ / 16, HID_);
    transpose_quant<<<dim3(HID_ / 32, HID_ / 32), 256>>>(w_o, cm2, bs2_p, wo1, wo0,
                                                         HID_, HID_);
    rope_table_kernel<<<T_, 128>>>(positions);

    // 1) QKV projection (int8 two-digit)
    gemm_i8<<<dim3(QKV_N_ / 128, T_ / 128), 512, IGEMM_SMEM>>>(
        ad1, ad0, wq1, wq0, as_p, bs1_p, qkv_ptr, T_, QKV_N_, HID_);

    // 2) RMSNorm + RoPE
    norm_rope_kernel<<<dim3(T_, NH_), 128>>>(q_norm_w, k_norm_w);

    // 3) Flash attention (fp32 out)
    attn_kernel<<<dim3(T_ / 32, NH_), 256, ATTN_SMEM_BYTES>>>();

    // 4) Quantize attention output, then O projection (int8 two-digit)
    quant_rows<<<T_, 256>>>(attn_ptr, cd1, cd0, cs_p, HID_);
    gemm_i8<<<dim3(HID_ / 128, T_ / 128), 512, IGEMM_SMEM>>>(
        cd1, cd0, wo1, wo0, cs_p, bs2_p, out, T_, HID_, HID_);
}

// round 14
// speedup vs baseline: 1.4540x; 1.0001x over previous
#include <cuda_runtime.h>
#include <cuda_bf16.h>
#include <math.h>
#include <stdint.h>

// Problem constants
#define T_   2048
#define HID_ 4096
#define NH_  16
#define D_   256
#define QKV_N_ (3 * HID_)   // 12288
#define EPS_ 1e-6f

// ---------------------------------------------------------------------------
// Scratch (device globals — no allocation allowed)
// ---------------------------------------------------------------------------
__device__ float    g_qkv [T_ * QKV_N_];      // fp32 qkv projection
__device__ float    g_attn[T_ * HID_];        // fp32 attention output
// int8 two-digit operands
__device__ char     g_ad1[T_ * HID_],      g_ad0[T_ * HID_];       // hidden
__device__ char     g_wq1[QKV_N_ * HID_],  g_wq0[QKV_N_ * HID_];   // w_qkv^T [N][K]
__device__ char     g_wo1[HID_ * HID_],    g_wo0[HID_ * HID_];     // w_o^T   [N][K]
__device__ char     g_cd1[T_ * HID_],      g_cd0[T_ * HID_];       // attn out
__device__ float    g_as[T_], g_cs[T_];                            // row scales
__device__ float    g_bs1[QKV_N_], g_bs2[HID_];                    // col scales
__device__ unsigned g_cmax1[QKV_N_], g_cmax2[HID_];                // col |max| bits
// attention inputs (packed bf16 hi/lo: (lo16<<16)|hi16)
__device__ uint32_t g_q32[NH_ * T_ * D_];
__device__ uint32_t g_k32[NH_ * T_ * D_];
__device__ uint32_t g_v32[NH_ * T_ * D_];
__device__ float2   g_rope[T_ * (D_ / 2)];

// ---------------------------------------------------------------------------
// Common helpers
// ---------------------------------------------------------------------------
__device__ __forceinline__ void split_bf16(float v, __nv_bfloat16& h, __nv_bfloat16& l) {
    h = __float2bfloat16(v);
    l = __float2bfloat16(v - __bfloat162float(h));
}
__device__ __forceinline__ uint32_t pack_split(float x) {
    __nv_bfloat16 hb, lb; split_bf16(x, hb, lb);
    return ((uint32_t)__bfloat16_as_ushort(lb) << 16) | (uint32_t)__bfloat16_as_ushort(hb);
}
#define MAIN2(u0, u1)  __byte_perm((u0), (u1), 0x5410)
#define RESID2(u0, u1) __byte_perm((u0), (u1), 0x7632)

__device__ __forceinline__ void mma_bf16(float c[4],
                                         uint32_t a0, uint32_t a1, uint32_t a2, uint32_t a3,
                                         uint32_t b0, uint32_t b1) {
    asm volatile(
        "mma.sync.aligned.m16n8k16.row.col.f32.bf16.bf16.f32 "
        "{%0,%1,%2,%3}, {%4,%5,%6,%7}, {%8,%9}, {%0,%1,%2,%3};"
        : "+f"(c[0]), "+f"(c[1]), "+f"(c[2]), "+f"(c[3])
        : "r"(a0), "r"(a1), "r"(a2), "r"(a3), "r"(b0), "r"(b1));
}

__device__ __forceinline__ void mma_s8(int c[4],
                                       uint32_t a0, uint32_t a1, uint32_t a2, uint32_t a3,
                                       uint32_t b0, uint32_t b1) {
    asm volatile(
        "mma.sync.aligned.m16n8k32.row.col.s32.s8.s8.s32 "
        "{%0,%1,%2,%3}, {%4,%5,%6,%7}, {%8,%9}, {%0,%1,%2,%3};"
        : "+r"(c[0]), "+r"(c[1]), "+r"(c[2]), "+r"(c[3])
        : "r"(a0), "r"(a1), "r"(a2), "r"(a3), "r"(b0), "r"(b1));
}

__device__ __forceinline__ void ldsm_x4(uint32_t r[4], uint32_t addr) {
    asm volatile("ldmatrix.sync.aligned.m8n8.x4.shared.b16 {%0,%1,%2,%3}, [%4];"
                 : "=r"(r[0]), "=r"(r[1]), "=r"(r[2]), "=r"(r[3]) : "r"(addr));
}

#define CP_ASYNC16(smem_u32, gptr) \
    asm volatile("cp.async.cg.shared.global [%0], [%1], 16;" :: "r"(smem_u32), "l"(gptr))
#define CP_COMMIT() asm volatile("cp.async.commit_group;")
#define CP_WAIT(n)  asm volatile("cp.async.wait_group %0;" :: "n"(n))

// quantize helper: v -> (d1, d0) with q = d1*128 + d0, |q| <= 16256
__device__ __forceinline__ void quant2(float v, float inv, char& d1, char& d0) {
    int q  = __float2int_rn(v * inv);
    int q1 = (q + 64) >> 7;          // round-to-nearest high digit
    d1 = (char)q1;
    d0 = (char)(q - (q1 << 7));      // in [-64, 63]
}

// ---------------------------------------------------------------------------
// prep_a: fused { quant_rows(hidden) | colmax(w_qkv) | colmax(w_o) | rope }.
// Grid 3328 x 256; block ranges select the job (whole block same branch).
// ---------------------------------------------------------------------------
#define PA_QR   2048                         // quant_rows blocks
#define PA_CM1  (PA_QR + 192)                // colmax w_qkv: 12 nblk x 16 kseg
#define PA_CM2  (PA_CM1 + 64)                // colmax w_o:    4 nblk x 16 kseg
#define PA_ROPE (PA_CM2 + 1024)              // rope: 1024 blocks x 2 rows

__global__ __launch_bounds__(256) void prep_a(
    const float* __restrict__ hidden, char* __restrict__ ad1, char* __restrict__ ad0,
    float* __restrict__ as_,
    const float* __restrict__ wqkv, unsigned* __restrict__ cm1,
    const float* __restrict__ wo,   unsigned* __restrict__ cm2,
    const int* __restrict__ positions)
{
    const int b = blockIdx.x;
    const int t = threadIdx.x;

    if (b < PA_QR) {
        // ---- quant rows of hidden: row = b, K = HID_ ----
        const int m = b;
        const float4* row = (const float4*)(hidden + (size_t)m * HID_);
        const int K4 = HID_ >> 2;
        float mx = 0.f;
        for (int i = t; i < K4; i += 256) {
            float4 v = row[i];
            mx = fmaxf(mx, fmaxf(fmaxf(fabsf(v.x), fabsf(v.y)), fmaxf(fabsf(v.z), fabsf(v.w))));
        }
        __shared__ float red[8];
        #pragma unroll
        for (int off = 16; off > 0; off >>= 1)
            mx = fmaxf(mx, __shfl_xor_sync(0xffffffff, mx, off));
        if ((t & 31) == 0) red[t >> 5] = mx;
        __syncthreads();
        mx = fmaxf(fmaxf(fmaxf(red[0], red[1]), fmaxf(red[2], red[3])),
                   fmaxf(fmaxf(red[4], red[5]), fmaxf(red[6], red[7])));
        const float mxg = fmaxf(mx, 1e-20f);
        const float inv = 16256.f / mxg;
        if (t == 0) as_[m] = mxg / 16256.f;
        char4* o1 = (char4*)(ad1 + (size_t)m * HID_);
        char4* o0 = (char4*)(ad0 + (size_t)m * HID_);
        for (int i = t; i < K4; i += 256) {
            float4 v = row[i];
            char a1, a0, b1, b0, c1, c0, e1, e0;
            quant2(v.x, inv, a1, a0); quant2(v.y, inv, b1, b0);
            quant2(v.z, inv, c1, c0); quant2(v.w, inv, e1, e0);
            o1[i] = make_char4(a1, b1, c1, e1);
            o0[i] = make_char4(a0, b0, c0, e0);
        }
    } else if (b < PA_CM1) {
        // ---- colmax w_qkv (float4 over N): N=12288, K=4096 ----
        const int bi = b - PA_QR;
        const int nb = bi % 12, kseg = bi / 12;
        const int c4 = nb * 256 + t;                 // float4 column index
        const int k0 = kseg * 256;
        float4 mx = make_float4(0.f, 0.f, 0.f, 0.f);
        for (int k = k0; k < k0 + 256; k++) {
            float4 v = ((const float4*)(wqkv + (size_t)k * QKV_N_))[c4];
            mx.x = fmaxf(mx.x, fabsf(v.x)); mx.y = fmaxf(mx.y, fabsf(v.y));
            mx.z = fmaxf(mx.z, fabsf(v.z)); mx.w = fmaxf(mx.w, fabsf(v.w));
        }
        atomicMax(cm1 + 4*c4 + 0, __float_as_uint(mx.x));
        atomicMax(cm1 + 4*c4 + 1, __float_as_uint(mx.y));
        atomicMax(cm1 + 4*c4 + 2, __float_as_uint(mx.z));
        atomicMax(cm1 + 4*c4 + 3, __float_as_uint(mx.w));
    } else if (b < PA_CM2) {
        // ---- colmax w_o: N=4096, K=4096 ----
        const int bi = b - PA_CM1;
        const int nb = bi % 4, kseg = bi / 4;
        const int c4 = nb * 256 + t;
        const int k0 = kseg * 256;
        float4 mx = make_float4(0.f, 0.f, 0.f, 0.f);
        for (int k = k0; k < k0 + 256; k++) {
            float4 v = ((const float4*)(wo + (size_t)k * HID_))[c4];
            mx.x = fmaxf(mx.x, fabsf(v.x)); mx.y = fmaxf(mx.y, fabsf(v.y));
            mx.z = fmaxf(mx.z, fabsf(v.z)); mx.w = fmaxf(mx.w, fabsf(v.w));
        }
        atomicMax(cm2 + 4*c4 + 0, __float_as_uint(mx.x));
        atomicMax(cm2 + 4*c4 + 1, __float_as_uint(mx.y));
        atomicMax(cm2 + 4*c4 + 2, __float_as_uint(mx.z));
        atomicMax(cm2 + 4*c4 + 3, __float_as_uint(mx.w));
    } else {
        // ---- rope: 2 rows per block ----
        const int bi = b - PA_CM2;
        const int tt = bi * 2 + (t >> 7);
        const int i  = t & 127;
        const int pos = positions[tt];
        const double inv_freq = exp(-(double)i * (2.0 / (double)D_) * log(10000.0));
        const float ang = (float)((double)pos * inv_freq);
        float s, c;
        sincosf(ang, &s, &c);
        g_rope[tt * 128 + i] = make_float2(c, s);
    }
}

// ---------------------------------------------------------------------------
// prep_b: fused transpose+quantize of both weights (flattened grid).
// ---------------------------------------------------------------------------
#define PB_W1 (384 * 128)    // w_qkv tiles

__global__ __launch_bounds__(256) void prep_b(
    const float* __restrict__ wqkv, const unsigned* __restrict__ cm1,
    float* __restrict__ bs1, char* __restrict__ wq1, char* __restrict__ wq0,
    const float* __restrict__ wo, const unsigned* __restrict__ cm2,
    float* __restrict__ bs2, char* __restrict__ wo1, char* __restrict__ wo0)
{
    const int b = blockIdx.x;
    const float* w; const unsigned* cmax; float* scales; char *d1p, *d0p;
    int bx, by, K, N;
    if (b < PB_W1) {
        w = wqkv; cmax = cm1; scales = bs1; d1p = wq1; d0p = wq0;
        K = HID_; N = QKV_N_; bx = b % 384; by = b / 384;
    } else {
        const int bi = b - PB_W1;
        w = wo; cmax = cm2; scales = bs2; d1p = wo1; d0p = wo0;
        K = HID_; N = HID_; bx = bi % 128; by = bi / 128;
    }

    __shared__ float tile[32][33];
    const int t  = threadIdx.x;
    const int tx = t & 31, ty = t >> 5;
    const int n0 = bx * 32, k0 = by * 32;

    #pragma unroll
    for (int j = 0; j < 4; j++)
        tile[ty + j * 8][tx] = w[(size_t)(k0 + ty + j * 8) * N + n0 + tx];
    if (ty == 0 && by == 0)
        scales[n0 + tx] = fmaxf(__uint_as_float(cmax[n0 + tx]), 1e-20f) / 16256.f;
    __syncthreads();

    const int nin = t >> 3;          // 0..31
    const int kq  = (t & 7) * 4;     // 0..28
    const float inv = 16256.f / fmaxf(__uint_as_float(cmax[n0 + nin]), 1e-20f);
    char a1, a0, b1, b0, c1, c0, e1, e0;
    quant2(tile[kq + 0][nin], inv, a1, a0);
    quant2(tile[kq + 1][nin], inv, b1, b0);
    quant2(tile[kq + 2][nin], inv, c1, c0);
    quant2(tile[kq + 3][nin], inv, e1, e0);
    *(char4*)(d1p + (size_t)(n0 + nin) * K + k0 + kq) = make_char4(a1, b1, c1, e1);
    *(char4*)(d0p + (size_t)(n0 + nin) * K + k0 + kq) = make_char4(a0, b0, c0, e0);
}

// ---------------------------------------------------------------------------
// Row quantization (for attention output before O-proj)
// ---------------------------------------------------------------------------
__global__ __launch_bounds__(256) void quant_rows(
    const float* __restrict__ src, char* __restrict__ d1p, char* __restrict__ d0p,
    float* __restrict__ scales, int K)
{
    const int m = blockIdx.x;
    const int t = threadIdx.x;
    const float4* row = (const float4*)(src + (size_t)m * K);
    const int K4 = K >> 2;

    float mx = 0.f;
    for (int i = t; i < K4; i += 256) {
        float4 v = row[i];
        mx = fmaxf(mx, fmaxf(fmaxf(fabsf(v.x), fabsf(v.y)), fmaxf(fabsf(v.z), fabsf(v.w))));
    }
    __shared__ float red[8];
    #pragma unroll
    for (int off = 16; off > 0; off >>= 1)
        mx = fmaxf(mx, __shfl_xor_sync(0xffffffff, mx, off));
    if ((t & 31) == 0) red[t >> 5] = mx;
    __syncthreads();
    mx = fmaxf(fmaxf(fmaxf(red[0], red[1]), fmaxf(red[2], red[3])),
               fmaxf(fmaxf(red[4], red[5]), fmaxf(red[6], red[7])));
    const float mxg = fmaxf(mx, 1e-20f);
    const float inv = 16256.f / mxg;
    if (t == 0) scales[m] = mxg / 16256.f;

    char4* o1 = (char4*)(d1p + (size_t)m * K);
    char4* o0 = (char4*)(d0p + (size_t)m * K);
    for (int i = t; i < K4; i += 256) {
        float4 v = row[i];
        char a1, a0, b1, b0, c1, c0, e1, e0;
        quant2(v.x, inv, a1, a0); quant2(v.y, inv, b1, b0);
        quant2(v.z, inv, c1, c0); quant2(v.w, inv, e1, e0);
        o1[i] = make_char4(a1, b1, c1, e1);
        o0[i] = make_char4(a0, b0, c0, e0);
    }
}

// ---------------------------------------------------------------------------
// int8 two-digit GEMM with ldmatrix feed.
// C_fp32[M,N] = (sa*sb) * qA[M,K] @ qB[N,K]^T
// 128x128 tile, BK=64, 512 threads (16 warps, 4x4 of 32x32), 2-stage cp.async.
// ---------------------------------------------------------------------------
#define ISTRIDE 80
#define IPL     (128 * ISTRIDE)     // 10240 bytes per digit plane
#define ISTAGE  (4 * IPL)           // 40960
#define IGEMM_SMEM (2 * ISTAGE)     // 81920

__global__ __launch_bounds__(512) void gemm_i8(
    const char* __restrict__ Ad1, const char* __restrict__ Ad0,
    const char* __restrict__ Bd1, const char* __restrict__ Bd0,
    const float* __restrict__ sa, const float* __restrict__ sb,
    float* __restrict__ C, int M, int N, int K)
{
    extern __shared__ char ism[];
    const uint32_t smb = (uint32_t)__cvta_generic_to_shared(ism);

    const int tid  = threadIdx.x;
    const int wid  = tid >> 5, lane = tid & 31;
    const int bm   = blockIdx.y * 128;
    const int bn   = blockIdx.x * 128;
    const int wm   = (wid >> 2) * 32;
    const int wn   = (wid & 3)  * 32;
    const int g    = lane >> 2;
    const int tig  = lane & 3;

    int P1[2][4][4], Pc[2][4][4];
    #pragma unroll
    for (int mf = 0; mf < 2; mf++)
        #pragma unroll
        for (int nf = 0; nf < 4; nf++)
            #pragma unroll
            for (int r = 0; r < 4; r++) { P1[mf][nf][r] = 0; Pc[mf][nf][r] = 0; }

    // loaders: each plane = 128 rows x 64B = 512 x 16B; 512 threads -> 1 each
    const int lr = tid >> 2;             // row 0..127
    const int lc = (tid & 3) * 16;       // 0,16,32,48
    auto load_chunk = [&](int stg, int c) {
        const int k0 = c * 64;
        const uint32_t tb = smb + stg * ISTAGE;
        const uint32_t off = (uint32_t)(lr * ISTRIDE + lc);
        const size_t ga = (size_t)(bm + lr) * K + k0 + lc;
        const size_t gb = (size_t)(bn + lr) * K + k0 + lc;
        CP_ASYNC16(tb + 0 * IPL + off, Ad1 + ga);
        CP_ASYNC16(tb + 1 * IPL + off, Ad0 + ga);
        CP_ASYNC16(tb + 2 * IPL + off, Bd1 + gb);
        CP_ASYNC16(tb + 3 * IPL + off, Bd0 + gb);
        CP_COMMIT();
    };

    const int NCH = K / 64;
    load_chunk(0, 0);

    // ldmatrix thread addressing
    const uint32_t a_off = (uint32_t)((wm + (lane & 15)) * ISTRIDE + (lane >> 4) * 16);
    const uint32_t b_off = (uint32_t)((wn + lane) * ISTRIDE);

    for (int c = 0; c < NCH; c++) {
        const int st = c & 1;
        if (c + 1 < NCH) { load_chunk(st ^ 1, c + 1); CP_WAIT(1); }
        else             { CP_WAIT(0); }
        __syncthreads();

        const uint32_t tbu = smb + st * ISTAGE;
        #pragma unroll
        for (int s = 0; s < 2; s++) {
            const uint32_t kb = s * 32;
            uint32_t a1[2][4], a0[2][4];
            #pragma unroll
            for (int mf = 0; mf < 2; mf++) {
                const uint32_t addr = tbu + a_off + kb + (uint32_t)(mf * 16 * ISTRIDE);
                ldsm_x4(a1[mf], addr);
                ldsm_x4(a0[mf], addr + IPL);
            }
            uint32_t bl1[4], bh1[4], bl0[4], bh0[4];
            {
                const uint32_t addr = tbu + 2 * IPL + b_off + kb;
                ldsm_x4(bl1, addr);
                ldsm_x4(bh1, addr + 16);
                ldsm_x4(bl0, addr + IPL);
                ldsm_x4(bh0, addr + IPL + 16);
            }
            #pragma unroll
            for (int nf = 0; nf < 4; nf++)
                #pragma unroll
                for (int mf = 0; mf < 2; mf++) {
                    mma_s8(P1[mf][nf], a1[mf][0], a1[mf][1], a1[mf][2], a1[mf][3],
                           bl1[nf], bh1[nf]);
                    mma_s8(Pc[mf][nf], a1[mf][0], a1[mf][1], a1[mf][2], a1[mf][3],
                           bl0[nf], bh0[nf]);
                    mma_s8(Pc[mf][nf], a0[mf][0], a0[mf][1], a0[mf][2], a0[mf][3],
                           bl1[nf], bh1[nf]);
                }
        }
        __syncthreads();
    }

    // epilogue: C = sa*sb*(16384*P1 + 128*Pc)
    #pragma unroll
    for (int mf = 0; mf < 2; mf++) {
        const int r0 = bm + wm + mf * 16 + g;
        const float sr0 = sa[r0], sr8 = sa[r0 + 8];
        #pragma unroll
        for (int nf = 0; nf < 4; nf++) {
            const int c0 = bn + wn + nf * 8 + 2 * tig;
            const float sc0 = sb[c0], sc1 = sb[c0 + 1];
            float v0 = sr0 * sc0 * fmaf(16384.f, (float)P1[mf][nf][0], 128.f * (float)Pc[mf][nf][0]);
            float v1 = sr0 * sc1 * fmaf(16384.f, (float)P1[mf][nf][1], 128.f * (float)Pc[mf][nf][1]);
            float v2 = sr8 * sc0 * fmaf(16384.f, (float)P1[mf][nf][2], 128.f * (float)Pc[mf][nf][2]);
            float v3 = sr8 * sc1 * fmaf(16384.f, (float)P1[mf][nf][3], 128.f * (float)Pc[mf][nf][3]);
            *(float2*)(C + (size_t)r0 * N + c0)       = make_float2(v0, v1);
            *(float2*)(C + (size_t)(r0 + 8) * N + c0) = make_float2(v2, v3);
        }
    }
}

// ---------------------------------------------------------------------------
// RMSNorm + RoPE; writes packed bf16-split q/k/v for the attention kernel.
// ---------------------------------------------------------------------------
__global__ __launch_bounds__(128) void norm_rope_kernel(
    const float* __restrict__ qw, const float* __restrict__ kw)
{
    const int t = blockIdx.x;
    const int h = blockIdx.y;
    const int i = threadIdx.x;

    const float* base = g_qkv + (size_t)t * QKV_N_ + h * D_;
    const float q0 = base[i],            q1 = base[i + 128];
    const float k0 = base[HID_ + i],     k1 = base[HID_ + i + 128];
    const float v0 = base[2*HID_ + i],   v1 = base[2*HID_ + i + 128];

    float sq = q0*q0 + q1*q1;
    float sk = k0*k0 + k1*k1;
    float sv = v0*v0 + v1*v1;

    __shared__ float redq[4], redk[4], redv[4];
    #pragma unroll
    for (int off = 16; off > 0; off >>= 1) {
        sq += __shfl_xor_sync(0xffffffff, sq, off);
        sk += __shfl_xor_sync(0xffffffff, sk, off);
        sv += __shfl_xor_sync(0xffffffff, sv, off);
    }
    const int warp = i >> 5, lane = i & 31;
    if (lane == 0) { redq[warp] = sq; redk[warp] = sk; redv[warp] = sv; }
    __syncthreads();
    sq = redq[0] + redq[1] + redq[2] + redq[3];
    sk = redk[0] + redk[1] + redk[2] + redk[3];
    sv = redv[0] + redv[1] + redv[2] + redv[3];

    const float rq = rsqrtf(sq * (1.f / D_) + EPS_);
    const float rk = rsqrtf(sk * (1.f / D_) + EPS_);
    const float rv = rsqrtf(sv * (1.f / D_) + EPS_);

    const float qn0 = q0 * rq * qw[i], qn1 = q1 * rq * qw[i + 128];
    const float kn0 = k0 * rk * kw[i], kn1 = k1 * rk * kw[i + 128];

    const float2 cs = g_rope[t * 128 + i];
    const float c = cs.x, s = cs.y;

    uint32_t* qo = g_q32 + ((size_t)h * T_ + t) * D_;
    uint32_t* ko = g_k32 + ((size_t)h * T_ + t) * D_;
    uint32_t* vo = g_v32 + ((size_t)h * T_ + t) * D_;

    qo[i]       = pack_split(qn0 * c - qn1 * s);
    qo[i + 128] = pack_split(qn1 * c + qn0 * s);
    ko[i]       = pack_split(kn0 * c - kn1 * s);
    ko[i + 128] = pack_split(kn1 * c + kn0 * s);
    vo[i]       = pack_split(v0 * rv);
    vo[i + 128] = pack_split(v1 * rv);
}

// ---------------------------------------------------------------------------
// Tensor-core flash attention (R4-proven), bf16-split; emits fp32 g_attn.
// Grid (T/32, NH), 256 threads.
// ---------------------------------------------------------------------------
#define QSTRIDE 260
#define SSTRIDE 36
#define OFF_Q   0
#define OFF_K   (32 * QSTRIDE)
#define OFF_V   (OFF_K + 2 * 32 * QSTRIDE)
#define OFF_S   (OFF_V + 2 * 32 * QSTRIDE)
#define OFF_M   (OFF_S + 32 * SSTRIDE)
#define OFF_L   (OFF_M + 32)
#define OFF_A   (OFF_L + 32)
#define ATTN_SMEM_BYTES ((OFF_A + 32) * 4)

__global__ __launch_bounds__(256) void attn_kernel()
{
    extern __shared__ uint32_t sm[];
    uint32_t* Qs = sm + OFF_Q;
    uint32_t* Ks = sm + OFF_K;
    uint32_t* Vs = sm + OFF_V;
    float*    Ss = (float*)(sm + OFF_S);
    float*    mS = (float*)(sm + OFF_M);
    float*    lS = (float*)(sm + OFF_L);
    float*    aS = (float*)(sm + OFF_A);

    const int bx = blockIdx.x;
    const int h  = blockIdx.y;
    const int q0 = bx * 32;
    const int ntiles = bx + 1;

    const int tid  = threadIdx.x;
    const int wid  = tid >> 5, lane = tid & 31;
    const int g    = lane >> 2;
    const int tig  = lane & 3;

    {
        const uint32_t* qsrc = g_q32 + ((size_t)h * T_ + q0) * D_;
        #pragma unroll
        for (int i = tid; i < 2048; i += 256) {
            int r = i >> 6, c = (i & 63) * 4;
            uint32_t dst = (uint32_t)__cvta_generic_to_shared(&Qs[r * QSTRIDE + c]);
            CP_ASYNC16(dst, qsrc + (size_t)r * D_ + c);
        }
    }
    auto load_kv = [&](int buf, int t) {
        const size_t base = ((size_t)h * T_ + t * 32) * D_;
        uint32_t* kd = Ks + buf * 32 * QSTRIDE;
        uint32_t* vd = Vs + buf * 32 * QSTRIDE;
        #pragma unroll
        for (int i = tid; i < 2048; i += 256) {
            int r = i >> 6, c = (i & 63) * 4;
            uint32_t dk = (uint32_t)__cvta_generic_to_shared(&kd[r * QSTRIDE + c]);
            CP_ASYNC16(dk, g_k32 + base + (size_t)r * D_ + c);
            uint32_t dv = (uint32_t)__cvta_generic_to_shared(&vd[r * QSTRIDE + c]);
            CP_ASYNC16(dv, g_v32 + base + (size_t)r * D_ + c);
        }
        CP_COMMIT();
    };
    load_kv(0, 0);

    if (tid < 32) { mS[tid] = -1e30f; lS[tid] = 0.f; }

    float oc[8][4];
    #pragma unroll
    for (int nf = 0; nf < 8; nf++)
        #pragma unroll
        for (int r = 0; r < 4; r++) oc[nf][r] = 0.f;

    const int wq = wid >> 2;
    const int wk = wid & 3;
    const int srow = tid >> 3;
    const int sl8  = tid & 7;

    for (int t = 0; t < ntiles; t++) {
        const int buf = t & 1;
        if (t + 1 < ntiles) { load_kv(buf ^ 1, t + 1); CP_WAIT(1); }
        else                { CP_WAIT(0); }
        __syncthreads();

        const uint32_t* Kb = Ks + buf * 32 * QSTRIDE;
        float c4[4] = {0.f, 0.f, 0.f, 0.f};
        #pragma unroll
        for (int ks = 0; ks < 16; ks++) {
            const int kc = ks * 16 + 2 * tig;
            uint2 ua0 = *(const uint2*)&Qs[(wq * 16 + g    ) * QSTRIDE + kc];
            uint2 ua1 = *(const uint2*)&Qs[(wq * 16 + g + 8) * QSTRIDE + kc];
            uint2 ua2 = *(const uint2*)&Qs[(wq * 16 + g    ) * QSTRIDE + kc + 8];
            uint2 ua3 = *(const uint2*)&Qs[(wq * 16 + g + 8) * QSTRIDE + kc + 8];
            uint32_t Ah0 = MAIN2(ua0.x, ua0.y), Al0 = RESID2(ua0.x, ua0.y);
            uint32_t Ah1 = MAIN2(ua1.x, ua1.y), Al1 = RESID2(ua1.x, ua1.y);
            uint32_t Ah2 = MAIN2(ua2.x, ua2.y), Al2 = RESID2(ua2.x, ua2.y);
            uint32_t Ah3 = MAIN2(ua3.x, ua3.y), Al3 = RESID2(ua3.x, ua3.y);
            uint2 ub0 = *(const uint2*)&Kb[(wk * 8 + g) * QSTRIDE + kc];
            uint2 ub1 = *(const uint2*)&Kb[(wk * 8 + g) * QSTRIDE + kc + 8];
            uint32_t Bh0 = MAIN2(ub0.x, ub0.y), Bl0 = RESID2(ub0.x, ub0.y);
            uint32_t Bh1 = MAIN2(ub1.x, ub1.y), Bl1 = RESID2(ub1.x, ub1.y);
            mma_bf16(c4, Ah0, Ah1, Ah2, Ah3, Bl0, Bl1);
            mma_bf16(c4, Al0, Al1, Al2, Al3, Bh0, Bh1);
            mma_bf16(c4, Ah0, Ah1, Ah2, Ah3, Bh0, Bh1);
        }
        {
            const int sc = wk * 8 + 2 * tig;
            Ss[(wq * 16 + g    ) * SSTRIDE + sc    ] = c4[0];
            Ss[(wq * 16 + g    ) * SSTRIDE + sc + 1] = c4[1];
            Ss[(wq * 16 + g + 8) * SSTRIDE + sc    ] = c4[2];
            Ss[(wq * 16 + g + 8) * SSTRIDE + sc + 1] = c4[3];
        }
        __syncthreads();

        {
            const int c0 = sl8 * 4;
            float4 sv = *(const float4*)&Ss[srow * SSTRIDE + c0];
            const bool lastmask = (t == bx);
            float s0 = sv.x, s1 = sv.y, s2 = sv.z, s3 = sv.w;
            bool v0 = !lastmask || (c0 + 0 <= srow);
            bool v1 = !lastmask || (c0 + 1 <= srow);
            bool v2 = !lastmask || (c0 + 2 <= srow);
            bool v3 = !lastmask || (c0 + 3 <= srow);
            float lmax = -1e30f;
            if (v0) lmax = fmaxf(lmax, s0);
            if (v1) lmax = fmaxf(lmax, s1);
            if (v2) lmax = fmaxf(lmax, s2);
            if (v3) lmax = fmaxf(lmax, s3);
            #pragma unroll
            for (int off = 4; off > 0; off >>= 1)
                lmax = fmaxf(lmax, __shfl_xor_sync(0xffffffff, lmax, off, 8));
            const float m_old = mS[srow];
            const float mnew  = fmaxf(m_old, lmax);
            float p0 = v0 ? __expf(s0 - mnew) : 0.f;
            float p1 = v1 ? __expf(s1 - mnew) : 0.f;
            float p2 = v2 ? __expf(s2 - mnew) : 0.f;
            float p3 = v3 ? __expf(s3 - mnew) : 0.f;
            float lsum = p0 + p1 + p2 + p3;
            #pragma unroll
            for (int off = 4; off > 0; off >>= 1)
                lsum += __shfl_xor_sync(0xffffffff, lsum, off, 8);
            uint32_t* Pp = (uint32_t*)&Ss[srow * SSTRIDE + c0];
            Pp[0] = pack_split(p0); Pp[1] = pack_split(p1);
            Pp[2] = pack_split(p2); Pp[3] = pack_split(p3);
            if (sl8 == 0) {
                const float alpha = __expf(m_old - mnew);
                mS[srow] = mnew;
                lS[srow] = lS[srow] * alpha + lsum;
                aS[srow] = alpha;
            }
        }
        __syncthreads();

        {
            const int wq2 = wid >> 2, wd = wid & 3;
            const float a_lo = aS[wq2 * 16 + g];
            const float a_hi = aS[wq2 * 16 + g + 8];
            #pragma unroll
            for (int nf = 0; nf < 8; nf++) {
                oc[nf][0] *= a_lo; oc[nf][1] *= a_lo;
                oc[nf][2] *= a_hi; oc[nf][3] *= a_hi;
            }
            const uint32_t* Vb = Vs + buf * 32 * QSTRIDE;
            const uint32_t* Pu = (const uint32_t*)Ss;
            #pragma unroll
            for (int ks = 0; ks < 2; ks++) {
                const int kc = ks * 16 + 2 * tig;
                uint2 up0 = *(const uint2*)&Pu[(wq2 * 16 + g    ) * SSTRIDE + kc];
                uint2 up1 = *(const uint2*)&Pu[(wq2 * 16 + g + 8) * SSTRIDE + kc];
                uint2 up2 = *(const uint2*)&Pu[(wq2 * 16 + g    ) * SSTRIDE + kc + 8];
                uint2 up3 = *(const uint2*)&Pu[(wq2 * 16 + g + 8) * SSTRIDE + kc + 8];
                uint32_t Ah0 = MAIN2(up0.x, up0.y), Al0 = RESID2(up0.x, up0.y);
                uint32_t Ah1 = MAIN2(up1.x, up1.y), Al1 = RESID2(up1.x, up1.y);
                uint32_t Ah2 = MAIN2(up2.x, up2.y), Al2 = RESID2(up2.x, up2.y);
                uint32_t Ah3 = MAIN2(up3.x, up3.y), Al3 = RESID2(up3.x, up3.y);
                #pragma unroll
                for (int nf = 0; nf < 8; nf++) {
                    const int n0 = wd * 64 + nf * 8 + g;
                    uint32_t v0 = Vb[(kc    ) * QSTRIDE + n0];
                    uint32_t v1 = Vb[(kc + 1) * QSTRIDE + n0];
                    uint32_t v2 = Vb[(kc + 8) * QSTRIDE + n0];
                    uint32_t v3 = Vb[(kc + 9) * QSTRIDE + n0];
                    uint32_t Bh0 = MAIN2(v0, v1), Bl0 = RESID2(v0, v1);
                    uint32_t Bh1 = MAIN2(v2, v3), Bl1 = RESID2(v2, v3);
                    mma_bf16(oc[nf], Ah0, Ah1, Ah2, Ah3, Bl0, Bl1);
                    mma_bf16(oc[nf], Al0, Al1, Al2, Al3, Bh0, Bh1);
                    mma_bf16(oc[nf], Ah0, Ah1, Ah2, Ah3, Bh0, Bh1);
                }
            }
        }
        __syncthreads();
    }

    // finalize: O / l -> fp32 g_attn
    {
        const int wq2 = wid >> 2, wd = wid & 3;
        const float inv_lo = 1.f / lS[wq2 * 16 + g];
        const float inv_hi = 1.f / lS[wq2 * 16 + g + 8];
        const int r_lo = q0 + wq2 * 16 + g;
        const int r_hi = r_lo + 8;
        #pragma unroll
        for (int nf = 0; nf < 8; nf++) {
            const int n = h * D_ + wd * 64 + nf * 8 + 2 * tig;
            *(float2*)&g_attn[(size_t)r_lo * HID_ + n] =
                make_float2(oc[nf][0] * inv_lo, oc[nf][1] * inv_lo);
            *(float2*)&g_attn[(size_t)r_hi * HID_ + n] =
                make_float2(oc[nf][2] * inv_hi, oc[nf][3] * inv_hi);
        }
    }
}

// ---------------------------------------------------------------------------
// Launch
// ---------------------------------------------------------------------------
extern "C" void kernel_launch(void* const* d_in, const int* in_sizes, int n_in,
                              void* d_out, int out_size)
{
    const float* hidden    = (const float*)d_in[0];
    const int*   positions = (const int*)  d_in[1];
    const float* w_qkv     = (const float*)d_in[2];
    const float* w_o       = (const float*)d_in[3];
    const float* q_norm_w  = (const float*)d_in[4];
    const float* k_norm_w  = (const float*)d_in[5];
    float* out = (float*)d_out;

    float *qkv_ptr, *attn_ptr, *as_p, *cs_p, *bs1_p, *bs2_p;
    char *ad1, *ad0, *wq1, *wq0, *wo1, *wo0, *cd1, *cd0;
    unsigned *cm1, *cm2;
    cudaGetSymbolAddress((void**)&qkv_ptr,  g_qkv);
    cudaGetSymbolAddress((void**)&attn_ptr, g_attn);
    cudaGetSymbolAddress((void**)&ad1, g_ad1);  cudaGetSymbolAddress((void**)&ad0, g_ad0);
    cudaGetSymbolAddress((void**)&wq1, g_wq1);  cudaGetSymbolAddress((void**)&wq0, g_wq0);
    cudaGetSymbolAddress((void**)&wo1, g_wo1);  cudaGetSymbolAddress((void**)&wo0, g_wo0);
    cudaGetSymbolAddress((void**)&cd1, g_cd1);  cudaGetSymbolAddress((void**)&cd0, g_cd0);
    cudaGetSymbolAddress((void**)&as_p, g_as);  cudaGetSymbolAddress((void**)&cs_p, g_cs);
    cudaGetSymbolAddress((void**)&bs1_p, g_bs1); cudaGetSymbolAddress((void**)&bs2_p, g_bs2);
    cudaGetSymbolAddress((void**)&cm1, g_cmax1); cudaGetSymbolAddress((void**)&cm2, g_cmax2);

    cudaFuncSetAttribute(attn_kernel, cudaFuncAttributeMaxDynamicSharedMemorySize,
                         ATTN_SMEM_BYTES);
    cudaFuncSetAttribute(gemm_i8, cudaFuncAttributeMaxDynamicSharedMemorySize,
                         IGEMM_SMEM);

    // Prepass (fused): quantize activations + column maxima + rope table
    cudaMemsetAsync(cm1, 0, QKV_N_ * sizeof(unsigned));
    cudaMemsetAsync(cm2, 0, HID_ * sizeof(unsigned));
    prep_a<<<PA_ROPE, 256>>>(hidden, ad1, ad0, as_p, w_qkv, cm1, w_o, cm2, positions);
    prep_b<<<PB_W1 + 128 * 128, 256>>>(w_qkv, cm1, bs1_p, wq1, wq0,
                                       w_o, cm2, bs2_p, wo1, wo0);

    // 1) QKV projection (int8 two-digit, ldmatrix feed)
    gemm_i8<<<dim3(QKV_N_ / 128, T_ / 128), 512, IGEMM_SMEM>>>(
        ad1, ad0, wq1, wq0, as_p, bs1_p, qkv_ptr, T_, QKV_N_, HID_);

    // 2) RMSNorm + RoPE
    norm_rope_kernel<<<dim3(T_, NH_), 128>>>(q_norm_w, k_norm_w);

    // 3) Flash attention (fp32 out)
    attn_kernel<<<dim3(T_ / 32, NH_), 256, ATTN_SMEM_BYTES>>>();

    // 4) Quantize attention output, then O projection
    quant_rows<<<T_, 256>>>(attn_ptr, cd1, cd0, cs_p, HID_);
    gemm_i8<<<dim3(HID_ / 128, T_ / 128), 512, IGEMM_SMEM>>>(
        cd1, cd0, wo1, wo0, cs_p, bs2_p, out, T_, HID_, HID_);
}